// round 12
// baseline (speedup 1.0000x reference)
#include <cuda_runtime.h>
#include <cuda_bf16.h>
#include <cstdint>

#define BSZ 4
#define SEQ 2048
#define EMB 1024
#define HD  64
#define MTOT (BSZ * SEQ)

// bf16 split weights (x converted inside the GEMM)
__device__ __nv_bfloat16 w_hi[192 * EMB];
__device__ __nv_bfloat16 w_lo[192 * EMB];
// projection outputs: Q,K transposed [dim][global row], V row-major
__device__ float g_qT[HD * MTOT];
__device__ float g_kT[HD * MTOT];
__device__ float g_vs[MTOT * HD];
// vmean
__device__ float g_vpart[BSZ * 32 * HD];
__device__ float g_vmean[BSZ * HD];
// attention split-key partials: 320 jobs (80 per batch, 512-key chunks)
#define NJOBS 320
__device__ float g_pm[NJOBS * 64];
__device__ float g_pl[NJOBS * 64];
__device__ float g_po[NJOBS * 64 * 64];

typedef unsigned long long u64;

__device__ __forceinline__ u64 splat2(float x) {
    u64 r; asm("mov.b64 %0, {%1, %1};" : "=l"(r) : "f"(x)); return r;
}
__device__ __forceinline__ u64 pack2(float lo, float hi) {
    u64 r; asm("mov.b64 %0, {%1, %2};" : "=l"(r) : "f"(lo), "f"(hi)); return r;
}
__device__ __forceinline__ void fma2(u64& d, u64 a, u64 b) {
    asm("fma.rn.f32x2 %0, %1, %2, %0;" : "+l"(d) : "l"(a), "l"(b));
}
__device__ __forceinline__ void mul2(u64& d, u64 s) {
    asm("mul.rn.f32x2 %0, %0, %1;" : "+l"(d) : "l"(s));
}
__device__ __forceinline__ void unpack2(u64 v, float& lo, float& hi) {
    asm("mov.b64 {%0, %1}, %2;" : "=f"(lo), "=f"(hi) : "l"(v));
}
__device__ __forceinline__ uint32_t smem_u32(const void* p) {
    uint32_t a;
    asm("{ .reg .u64 t; cvta.to.shared.u64 t, %1; cvt.u32.u64 %0, t; }"
        : "=r"(a) : "l"(p));
    return a;
}

// ---- portable tensor-core helpers ----------------------------------------
__device__ __forceinline__ void mma_bf16(float* d, const uint32_t* a,
                                         const uint32_t* b) {
    asm volatile(
        "mma.sync.aligned.m16n8k16.row.col.f32.bf16.bf16.f32 "
        "{%0,%1,%2,%3}, {%4,%5,%6,%7}, {%8,%9}, {%0,%1,%2,%3};"
        : "+f"(d[0]), "+f"(d[1]), "+f"(d[2]), "+f"(d[3])
        : "r"(a[0]), "r"(a[1]), "r"(a[2]), "r"(a[3]), "r"(b[0]), "r"(b[1]));
}
__device__ __forceinline__ void ldsm4(uint32_t* r, uint32_t addr) {
    asm volatile("ldmatrix.sync.aligned.m8n8.x4.shared.b16 {%0,%1,%2,%3}, [%4];"
                 : "=r"(r[0]), "=r"(r[1]), "=r"(r[2]), "=r"(r[3]) : "r"(addr));
}
__device__ __forceinline__ void cp16(uint32_t smaddr, const void* g) {
    asm volatile("cp.async.ca.shared.global [%0], [%1], 16;"
                 :: "r"(smaddr), "l"(g));
}
#define CP_COMMIT()  asm volatile("cp.async.commit_group;" ::: "memory")
#define CP_WAIT(n)   asm volatile("cp.async.wait_group %0;" :: "n"(n) : "memory")

// ---- bf16 hi/lo split of a float4 ----------------------------------------
__device__ __forceinline__ void split4(float4 v, uint2& oh, uint2& ol) {
    __nv_bfloat16 h0 = __float2bfloat16_rn(v.x);
    __nv_bfloat16 h1 = __float2bfloat16_rn(v.y);
    __nv_bfloat16 h2 = __float2bfloat16_rn(v.z);
    __nv_bfloat16 h3 = __float2bfloat16_rn(v.w);
    __nv_bfloat16 l0 = __float2bfloat16_rn(v.x - __bfloat162float(h0));
    __nv_bfloat16 l1 = __float2bfloat16_rn(v.y - __bfloat162float(h1));
    __nv_bfloat16 l2 = __float2bfloat16_rn(v.z - __bfloat162float(h2));
    __nv_bfloat16 l3 = __float2bfloat16_rn(v.w - __bfloat162float(h3));
    oh.x = ((uint32_t)__bfloat16_as_ushort(h1) << 16) | __bfloat16_as_ushort(h0);
    oh.y = ((uint32_t)__bfloat16_as_ushort(h3) << 16) | __bfloat16_as_ushort(h2);
    ol.x = ((uint32_t)__bfloat16_as_ushort(l1) << 16) | __bfloat16_as_ushort(l0);
    ol.y = ((uint32_t)__bfloat16_as_ushort(l3) << 16) | __bfloat16_as_ushort(l2);
}

// ---------------------------------------------------------------------------
// Kernel B: convert stacked W -> hi/lo bf16.
// ---------------------------------------------------------------------------
__global__ __launch_bounds__(256) void convert_w_kernel(
    const float* __restrict__ Wq, const float* __restrict__ Wk,
    const float* __restrict__ Wv)
{
    const int row = blockIdx.x;
    const float* src = (row < 64) ? (Wq + (size_t)row * EMB)
                     : (row < 128) ? (Wk + (size_t)(row - 64) * EMB)
                                   : (Wv + (size_t)(row - 128) * EMB);
    const int i = threadIdx.x;
    float4 v = reinterpret_cast<const float4*>(src)[i];
    uint2 oh, ol;
    split4(v, oh, ol);
    reinterpret_cast<uint2*>(w_hi)[(size_t)row * (EMB / 4) + i] = oh;
    reinterpret_cast<uint2*>(w_lo)[(size_t)row * (EMB / 4) + i] = ol;
}

// ---------------------------------------------------------------------------
// Kernel C: QKV GEMM via mma.sync bf16 (3-term split), x converted in-kernel
// (round-10 fused version — measured faster than separate convert_x).
// grid 128, 256 threads (2 M x 4 N warps). Tile M=64, N=192, K chunks 64.
// ---------------------------------------------------------------------------
#define GPITCH 144
#define OFF_AH 0
#define OFF_AL 9216
#define OFF_BH 18432
#define OFF_BL 46080
#define GBUF   73728
#define GEMM_SMEM (2 * GBUF)
#define CHUNKS 16

__device__ __forceinline__ void ldA_chunk(float4* areg, const float* __restrict__ x,
                                          int c, int row0, int tid)
{
#pragma unroll
    for (int u = 0; u < 4; u++) {
        int idx = tid + u * 256, r = idx >> 4, seg = idx & 15;
        areg[u] = *reinterpret_cast<const float4*>(
            &x[(size_t)(row0 + r) * EMB + c * 64 + seg * 4]);
    }
}

__device__ __forceinline__ void stsA_chunk(char* buf, const float4* areg, int tid)
{
#pragma unroll
    for (int u = 0; u < 4; u++) {
        int idx = tid + u * 256, r = idx >> 4, seg = idx & 15;
        uint2 oh, ol;
        split4(areg[u], oh, ol);
        *reinterpret_cast<uint2*>(buf + OFF_AH + r * GPITCH + seg * 8) = oh;
        *reinterpret_cast<uint2*>(buf + OFF_AL + r * GPITCH + seg * 8) = ol;
    }
}

__device__ __forceinline__ void stage_B(uint32_t bufb, int c, int tid)
{
#pragma unroll
    for (int u = 0; u < 6; u++) {
        int idx = tid + u * 256, r = idx >> 3, seg = idx & 7;
        uint32_t dst = r * GPITCH + seg * 16;
        cp16(bufb + OFF_BH + dst, &w_hi[(size_t)r * EMB + c * 64 + seg * 8]);
        cp16(bufb + OFF_BL + dst, &w_lo[(size_t)r * EMB + c * 64 + seg * 8]);
    }
}

__global__ __launch_bounds__(256) void qkv_gemm_kernel(const float* __restrict__ x)
{
    extern __shared__ char smg[];
    const uint32_t smb = smem_u32(smg);
    const int tid  = threadIdx.x;
    const int lane = tid & 31;
    const int w    = tid >> 5;
    const int wm   = w & 1;
    const int wn   = w >> 1;
    const int row0 = blockIdx.x * 64;

    float acc[2][6][4];
#pragma unroll
    for (int mm = 0; mm < 2; mm++)
#pragma unroll
        for (int nn = 0; nn < 6; nn++)
#pragma unroll
            for (int q = 0; q < 4; q++) acc[mm][nn][q] = 0.f;

    const int g01 = (lane >> 3) & 1;
    const int g23 = (lane >> 4);
    const int tr  = lane & 7;

    float4 areg[4];
    ldA_chunk(areg, x, 0, row0, tid);
    stsA_chunk(smg, areg, tid);
    stage_B(smb, 0, tid);
    CP_COMMIT();

    for (int c = 0; c < CHUNKS; c++) {
        const uint32_t bufb = smb + (c & 1) * GBUF;
        if (c < CHUNKS - 1) {
            ldA_chunk(areg, x, c + 1, row0, tid);
            stage_B(smb + ((c + 1) & 1) * GBUF, c + 1, tid);
            CP_COMMIT();
            CP_WAIT(1);
        } else {
            CP_WAIT(0);
        }
        __syncthreads();

#pragma unroll
        for (int pass = 0; pass < 3; pass++) {
            const uint32_t aoff = (pass == 2) ? OFF_AL : OFF_AH;
            const uint32_t boff = (pass == 1) ? OFF_BL : OFF_BH;
#pragma unroll
            for (int ks = 0; ks < 4; ks++) {
                uint32_t afr[2][4];
#pragma unroll
                for (int mm = 0; mm < 2; mm++) {
                    uint32_t addr = bufb + aoff
                        + (uint32_t)(wm * 32 + mm * 16 + g01 * 8 + tr) * GPITCH
                        + (uint32_t)(ks * 16 + g23 * 8) * 2;
                    ldsm4(afr[mm], addr);
                }
                uint32_t bfr[3][4];
#pragma unroll
                for (int ng = 0; ng < 3; ng++) {
                    uint32_t addr = bufb + boff
                        + (uint32_t)(wn * 48 + ng * 16 + g23 * 8 + tr) * GPITCH
                        + (uint32_t)(ks * 16 + g01 * 8) * 2;
                    ldsm4(bfr[ng], addr);
                }
#pragma unroll
                for (int mm = 0; mm < 2; mm++)
#pragma unroll
                    for (int nn = 0; nn < 6; nn++)
                        mma_bf16(acc[mm][nn], afr[mm], &bfr[nn >> 1][(nn & 1) * 2]);
            }
        }
        if (c < CHUNKS - 1)
            stsA_chunk(smg + ((c + 1) & 1) * GBUF, areg, tid);
        __syncthreads();
    }

    // epilogue
    const int mrow = lane >> 2;
    const int ncol = 2 * (lane & 3);
#pragma unroll
    for (int mm = 0; mm < 2; mm++) {
#pragma unroll
        for (int nn = 0; nn < 6; nn++) {
            const int n = wn * 48 + nn * 8 + ncol;
            const int m = row0 + wm * 32 + mm * 16 + mrow;
            const float* cvals = acc[mm][nn];
            if (n < 64) {
                g_qT[(size_t)n * MTOT + m]           = cvals[0];
                g_qT[(size_t)(n + 1) * MTOT + m]     = cvals[1];
                g_qT[(size_t)n * MTOT + m + 8]       = cvals[2];
                g_qT[(size_t)(n + 1) * MTOT + m + 8] = cvals[3];
            } else if (n < 128) {
                const int nk = n - 64;
                g_kT[(size_t)nk * MTOT + m]           = cvals[0];
                g_kT[(size_t)(nk + 1) * MTOT + m]     = cvals[1];
                g_kT[(size_t)nk * MTOT + m + 8]       = cvals[2];
                g_kT[(size_t)(nk + 1) * MTOT + m + 8] = cvals[3];
            } else {
                const int nv = n - 128;
                *reinterpret_cast<float2*>(&g_vs[(size_t)m * HD + nv]) =
                    make_float2(cvals[0], cvals[1]);
                *reinterpret_cast<float2*>(&g_vs[(size_t)(m + 8) * HD + nv]) =
                    make_float2(cvals[2], cvals[3]);
            }
        }
    }
}

// ---------------------------------------------------------------------------
// Kernel D: per-batch mean of V rows (parallel version, measured 10.5us).
// ---------------------------------------------------------------------------
__global__ __launch_bounds__(256) void vmean1_kernel()
{
    const int b = blockIdx.x;
    const int c = blockIdx.y;                // 64-row chunk
    const int d = threadIdx.x & 63;
    const int sub = threadIdx.x >> 6;
    float s = 0.f;
    const int i0 = c * 64 + sub * 16;
#pragma unroll 4
    for (int i = i0; i < i0 + 16; i++)
        s += g_vs[((size_t)b * SEQ + i) * HD + d];
    __shared__ float red[256];
    red[threadIdx.x] = s;
    __syncthreads();
    if (sub == 0)
        g_vpart[(b * 32 + c) * HD + d] =
            red[d] + red[64 + d] + red[128 + d] + red[192 + d];
}

__global__ __launch_bounds__(256) void vmean2_kernel()
{
    const int b = blockIdx.x;
    const int d = threadIdx.x & 63;
    const int sub = threadIdx.x >> 6;
    float s = 0.f;
#pragma unroll
    for (int c = sub * 8; c < sub * 8 + 8; c++)
        s += g_vpart[(b * 32 + c) * HD + d];
    __shared__ float red[256];
    red[threadIdx.x] = s;
    __syncthreads();
    if (sub == 0)
        g_vmean[b * HD + d] =
            (red[d] + red[64 + d] + red[128 + d] + red[192 + d]) * (1.0f / SEQ);
}

// ---------------------------------------------------------------------------
// Kernel E: attention partials — round-8 configuration verbatim.
// Jobs: (batch, 64-row q-tile, <=512-key chunk) -> 80/batch, 320 total.
// 118KB smem, 1 block/SM, 8 warps x 8 rows.
// ---------------------------------------------------------------------------
#define PQ2 68
#define PK2 132
#define PV2 68
#define PP2 68

#define A_QT 0
#define A_KT (A_QT + 64 * PQ2)
#define A_V  (A_KT + 64 * PK2)
#define A_PT (A_V + 128 * PV2)
#define ATTN_SMEM ((A_PT + 128 * PP2) * 4)

__global__ __launch_bounds__(256) void attn_partial_kernel(
    const int* __restrict__ pad)
{
    const int bid = blockIdx.x;
    const int b = bid / 80;
    const int rem = bid - b * 80;
    int jq, ch;
    if (rem < 8)       { jq = rem;                   ch = 0; }
    else if (rem < 24) { jq = 8 + ((rem - 8) >> 1);  ch = (rem - 8) & 1; }
    else if (rem < 48) { jq = 16 + (rem - 24) / 3;   ch = (rem - 24) % 3; }
    else               { jq = 24 + ((rem - 48) >> 2); ch = (rem - 48) & 3; }
    const int q0 = jq * 64;
    const int kstart = ch * 512;
    const int kmax = q0 + 64;
    const int kend = (kstart + 512 < kmax) ? kstart + 512 : kmax;
    const int nkt = (kend - kstart + 127) >> 7;

    const int tid  = threadIdx.x;
    const int lane = tid & 31;
    const int ty8  = (tid >> 5) * 8;

    extern __shared__ float smem[];
    float* sQt = smem + A_QT;
    float* sKt = smem + A_KT;
    float* sV  = smem + A_V;
    float* sPt = smem + A_PT;
    __shared__ int sPad[128];

#pragma unroll
    for (int u = 0; u < 4; u++) {
        int idx = tid + u * 256;
        int d = idx >> 4, f = (idx & 15) * 4;
        float4 v4 = *reinterpret_cast<const float4*>(
            &g_qT[(size_t)d * MTOT + b * SEQ + q0 + f]);
        *reinterpret_cast<float4*>(&sQt[d * PQ2 + f]) = v4;
    }

    float m[8], l[8];
    u64 o2[4][2];
#pragma unroll
    for (int r = 0; r < 8; r++) { m[r] = -3.0e38f; l[r] = 0.f; }
#pragma unroll
    for (int p = 0; p < 4; p++) { o2[p][0] = 0ULL; o2[p][1] = 0ULL; }

    for (int kt = 0; kt < nkt; kt++) {
        const int k0 = kstart + kt * 128;
        __syncthreads();

#pragma unroll
        for (int u = 0; u < 8; u++) {
            int idx = tid + u * 256;
            int d = idx >> 5, f = (idx & 31) * 4;
            float4 v4 = *reinterpret_cast<const float4*>(
                &g_kT[(size_t)d * MTOT + b * SEQ + k0 + f]);
            *reinterpret_cast<float4*>(&sKt[d * PK2 + f]) = v4;
        }
#pragma unroll
        for (int u = 0; u < 8; u++) {
            int idx = tid + u * 256;
            int r = idx >> 4, f = (idx & 15) * 4;
            float4 a = *reinterpret_cast<const float4*>(
                &g_vs[((size_t)b * SEQ + k0 + r) * HD + f]);
            *reinterpret_cast<float4*>(&sV[r * PV2 + f]) = a;
        }
        if (tid < 128) sPad[tid] = pad[b * SEQ + k0 + tid];
        __syncthreads();

        u64 s2[4][4];
#pragma unroll
        for (int p = 0; p < 4; p++)
#pragma unroll
            for (int i = 0; i < 4; i++) s2[p][i] = 0ULL;
#pragma unroll 8
        for (int d = 0; d < 64; d++) {
            ulonglong2 qA = *reinterpret_cast<const ulonglong2*>(&sQt[d * PQ2 + ty8]);
            ulonglong2 qB = *reinterpret_cast<const ulonglong2*>(&sQt[d * PQ2 + ty8 + 4]);
            float4 kv = *reinterpret_cast<const float4*>(&sKt[d * PK2 + lane * 4]);
            u64 k0s = splat2(kv.x), k1s = splat2(kv.y);
            u64 k2s = splat2(kv.z), k3s = splat2(kv.w);
            fma2(s2[0][0], qA.x, k0s); fma2(s2[0][1], qA.x, k1s);
            fma2(s2[0][2], qA.x, k2s); fma2(s2[0][3], qA.x, k3s);
            fma2(s2[1][0], qA.y, k0s); fma2(s2[1][1], qA.y, k1s);
            fma2(s2[1][2], qA.y, k2s); fma2(s2[1][3], qA.y, k3s);
            fma2(s2[2][0], qB.x, k0s); fma2(s2[2][1], qB.x, k1s);
            fma2(s2[2][2], qB.x, k2s); fma2(s2[2][3], qB.x, k3s);
            fma2(s2[3][0], qB.y, k0s); fma2(s2[3][1], qB.y, k1s);
            fma2(s2[3][2], qB.y, k2s); fma2(s2[3][3], qB.y, k3s);
        }

        float sv[8][4];
#pragma unroll
        for (int p = 0; p < 4; p++)
#pragma unroll
            for (int i = 0; i < 4; i++)
                unpack2(s2[p][i], sv[2 * p][i], sv[2 * p + 1][i]);

        float p8[8][4], scl[8];
#pragma unroll
        for (int r = 0; r < 8; r++) {
            const int qi = q0 + ty8 + r;
#pragma unroll
            for (int i = 0; i < 4; i++) {
                const int kj = k0 + lane * 4 + i;
                const bool masked = (kj > qi) || (sPad[lane * 4 + i] == 0);
                sv[r][i] = (masked ? -1e9f : sv[r][i]) * 0.125f;
            }
            float tm = fmaxf(fmaxf(sv[r][0], sv[r][1]), fmaxf(sv[r][2], sv[r][3]));
            tm = fmaxf(tm, __shfl_xor_sync(0xffffffffu, tm, 1));
            tm = fmaxf(tm, __shfl_xor_sync(0xffffffffu, tm, 2));
            tm = fmaxf(tm, __shfl_xor_sync(0xffffffffu, tm, 4));
            tm = fmaxf(tm, __shfl_xor_sync(0xffffffffu, tm, 8));
            tm = fmaxf(tm, __shfl_xor_sync(0xffffffffu, tm, 16));
            const float mnew = fmaxf(m[r], tm);
            scl[r] = __expf(m[r] - mnew);
            float tl = 0.f;
#pragma unroll
            for (int i = 0; i < 4; i++) { p8[r][i] = __expf(sv[r][i] - mnew); tl += p8[r][i]; }
            tl += __shfl_xor_sync(0xffffffffu, tl, 1);
            tl += __shfl_xor_sync(0xffffffffu, tl, 2);
            tl += __shfl_xor_sync(0xffffffffu, tl, 4);
            tl += __shfl_xor_sync(0xffffffffu, tl, 8);
            tl += __shfl_xor_sync(0xffffffffu, tl, 16);
            l[r] = l[r] * scl[r] + tl;
            m[r] = mnew;
        }
#pragma unroll
        for (int p = 0; p < 4; p++) {
            u64 sp = pack2(scl[2 * p], scl[2 * p + 1]);
            mul2(o2[p][0], sp);
            mul2(o2[p][1], sp);
        }
#pragma unroll
        for (int i = 0; i < 4; i++) {
            const int key = lane * 4 + i;
            *reinterpret_cast<float4*>(&sPt[key * PP2 + ty8]) =
                make_float4(p8[0][i], p8[1][i], p8[2][i], p8[3][i]);
            *reinterpret_cast<float4*>(&sPt[key * PP2 + ty8 + 4]) =
                make_float4(p8[4][i], p8[5][i], p8[6][i], p8[7][i]);
        }
        __syncthreads();

#pragma unroll 8
        for (int j = 0; j < 128; j++) {
            ulonglong2 pA = *reinterpret_cast<const ulonglong2*>(&sPt[j * PP2 + ty8]);
            ulonglong2 pB = *reinterpret_cast<const ulonglong2*>(&sPt[j * PP2 + ty8 + 4]);
            float2 v2 = *reinterpret_cast<const float2*>(&sV[j * PV2 + lane * 2]);
            u64 v0 = splat2(v2.x), v1 = splat2(v2.y);
            fma2(o2[0][0], pA.x, v0); fma2(o2[0][1], pA.x, v1);
            fma2(o2[1][0], pA.y, v0); fma2(o2[1][1], pA.y, v1);
            fma2(o2[2][0], pB.x, v0); fma2(o2[2][1], pB.x, v1);
            fma2(o2[3][0], pB.y, v0); fma2(o2[3][1], pB.y, v1);
        }
    }

    if (lane == 0) {
#pragma unroll
        for (int r = 0; r < 8; r++) {
            g_pm[bid * 64 + ty8 + r] = m[r];
            g_pl[bid * 64 + ty8 + r] = l[r];
        }
    }
#pragma unroll
    for (int p = 0; p < 4; p++) {
        float aLo, aHi, bLo, bHi;
        unpack2(o2[p][0], aLo, aHi);
        unpack2(o2[p][1], bLo, bHi);
        *reinterpret_cast<float2*>(
            &g_po[(size_t)bid * 4096 + (ty8 + 2 * p) * 64 + lane * 2]) =
            make_float2(aLo, bLo);
        *reinterpret_cast<float2*>(
            &g_po[(size_t)bid * 4096 + (ty8 + 2 * p + 1) * 64 + lane * 2]) =
            make_float2(aHi, bHi);
    }
}

// ---------------------------------------------------------------------------
// Kernel F: merge partials (round-8 version).
// ---------------------------------------------------------------------------
__global__ __launch_bounds__(256) void attn_merge_kernel(float* __restrict__ out)
{
    const int b  = blockIdx.x >> 5;
    const int jq = blockIdx.x & 31;
    int off;
    if (jq < 8)       off = jq;
    else if (jq < 16) off = 8 + 2 * (jq - 8);
    else if (jq < 24) off = 24 + 3 * (jq - 16);
    else              off = 48 + 4 * (jq - 24);
    const int nch = (jq >> 3) + 1;
    const int jbase = b * 80 + off;
    const int q0 = jq * 64;

    const int d  = threadIdx.x & 63;
    const int r0 = threadIdx.x >> 6;

    for (int rr = 0; rr < 16; rr++) {
        const int row = r0 + rr * 4;
        float M = -3.0e38f;
        float mi[5], li[5];
#pragma unroll 5
        for (int i = 0; i < 5; i++) {
            if (i < nch) {
                mi[i] = g_pm[(jbase + i) * 64 + row];
                li[i] = g_pl[(jbase + i) * 64 + row];
                M = fmaxf(M, mi[i]);
            }
        }
        float L = 0.f, O = 0.f;
#pragma unroll 5
        for (int i = 0; i < 5; i++) {
            if (i < nch) {
                float w = __expf(mi[i] - M);
                L += li[i] * w;
                O += g_po[(size_t)(jbase + i) * 4096 + row * 64 + d] * w;
            }
        }
        float res = (M <= -1.0e8f) ? g_vmean[b * HD + d] : O / L;
        out[((size_t)b * SEQ + q0 + row) * HD + d] = res;
    }
}

// ---------------------------------------------------------------------------
extern "C" void kernel_launch(void* const* d_in, const int* in_sizes, int n_in,
                              void* d_out, int out_size)
{
    const float* x   = (const float*)d_in[0];
    const int*   pad = (const int*)  d_in[1];
    const float* Wq  = (const float*)d_in[2];
    const float* Wk  = (const float*)d_in[3];
    const float* Wv  = (const float*)d_in[4];
    float* out = (float*)d_out;

    cudaFuncSetAttribute(qkv_gemm_kernel,
                         cudaFuncAttributeMaxDynamicSharedMemorySize, GEMM_SMEM);
    cudaFuncSetAttribute(attn_partial_kernel,
                         cudaFuncAttributeMaxDynamicSharedMemorySize, ATTN_SMEM);

    convert_w_kernel<<<192, 256>>>(Wq, Wk, Wv);
    qkv_gemm_kernel<<<128, 256, GEMM_SMEM>>>(x);
    vmean1_kernel<<<dim3(BSZ, 32), 256>>>();
    vmean2_kernel<<<BSZ, 256>>>();
    attn_partial_kernel<<<NJOBS, 256, ATTN_SMEM>>>(pad);
    attn_merge_kernel<<<128, 256>>>(out);
}

// round 13
// speedup vs baseline: 1.5025x; 1.5025x over previous
#include <cuda_runtime.h>
#include <cuda_bf16.h>
#include <cstdint>

#define BSZ 4
#define SEQ 2048
#define EMB 1024
#define HD  64
#define MTOT (BSZ * SEQ)

// bf16 split operands
__device__ __nv_bfloat16 x_hi[MTOT * EMB];
__device__ __nv_bfloat16 x_lo[MTOT * EMB];
__device__ __nv_bfloat16 w_hi[192 * EMB];
__device__ __nv_bfloat16 w_lo[192 * EMB];
// projection outputs: Q,K transposed [dim][global row], V row-major
__device__ float g_qT[HD * MTOT];
__device__ float g_kT[HD * MTOT];
__device__ float g_vs[MTOT * HD];
// vmean
__device__ float g_vpart[BSZ * 32 * HD];
__device__ float g_vmean[BSZ * HD];
// attention split-key partials: 320 jobs (80 per batch, 512-key chunks)
#define NJOBS 320
__device__ float g_pm[NJOBS * 64];
__device__ float g_pl[NJOBS * 64];
__device__ float g_po[NJOBS * 64 * 64];

typedef unsigned long long u64;

__device__ __forceinline__ u64 splat2(float x) {
    u64 r; asm("mov.b64 %0, {%1, %1};" : "=l"(r) : "f"(x)); return r;
}
__device__ __forceinline__ u64 pack2(float lo, float hi) {
    u64 r; asm("mov.b64 %0, {%1, %2};" : "=l"(r) : "f"(lo), "f"(hi)); return r;
}
__device__ __forceinline__ void fma2(u64& d, u64 a, u64 b) {
    asm("fma.rn.f32x2 %0, %1, %2, %0;" : "+l"(d) : "l"(a), "l"(b));
}
__device__ __forceinline__ void mul2(u64& d, u64 s) {
    asm("mul.rn.f32x2 %0, %0, %1;" : "+l"(d) : "l"(s));
}
__device__ __forceinline__ void unpack2(u64 v, float& lo, float& hi) {
    asm("mov.b64 {%0, %1}, %2;" : "=f"(lo), "=f"(hi) : "l"(v));
}
__device__ __forceinline__ uint32_t smem_u32(const void* p) {
    uint32_t a;
    asm("{ .reg .u64 t; cvta.to.shared.u64 t, %1; cvt.u32.u64 %0, t; }"
        : "=r"(a) : "l"(p));
    return a;
}

// ---- portable tensor-core helpers ----------------------------------------
__device__ __forceinline__ void mma_bf16(float* d, const uint32_t* a,
                                         const uint32_t* b) {
    asm volatile(
        "mma.sync.aligned.m16n8k16.row.col.f32.bf16.bf16.f32 "
        "{%0,%1,%2,%3}, {%4,%5,%6,%7}, {%8,%9}, {%0,%1,%2,%3};"
        : "+f"(d[0]), "+f"(d[1]), "+f"(d[2]), "+f"(d[3])
        : "r"(a[0]), "r"(a[1]), "r"(a[2]), "r"(a[3]), "r"(b[0]), "r"(b[1]));
}
__device__ __forceinline__ void ldsm4(uint32_t* r, uint32_t addr) {
    asm volatile("ldmatrix.sync.aligned.m8n8.x4.shared.b16 {%0,%1,%2,%3}, [%4];"
                 : "=r"(r[0]), "=r"(r[1]), "=r"(r[2]), "=r"(r[3]) : "r"(addr));
}
__device__ __forceinline__ void cp16(uint32_t smaddr, const void* g) {
    asm volatile("cp.async.ca.shared.global [%0], [%1], 16;"
                 :: "r"(smaddr), "l"(g));
}
#define CP_COMMIT()  asm volatile("cp.async.commit_group;" ::: "memory")
#define CP_WAIT(n)   asm volatile("cp.async.wait_group %0;" :: "n"(n) : "memory")

// ---- bf16 hi/lo split of a float4 ----------------------------------------
__device__ __forceinline__ void split4(float4 v, uint2& oh, uint2& ol) {
    __nv_bfloat16 h0 = __float2bfloat16_rn(v.x);
    __nv_bfloat16 h1 = __float2bfloat16_rn(v.y);
    __nv_bfloat16 h2 = __float2bfloat16_rn(v.z);
    __nv_bfloat16 h3 = __float2bfloat16_rn(v.w);
    __nv_bfloat16 l0 = __float2bfloat16_rn(v.x - __bfloat162float(h0));
    __nv_bfloat16 l1 = __float2bfloat16_rn(v.y - __bfloat162float(h1));
    __nv_bfloat16 l2 = __float2bfloat16_rn(v.z - __bfloat162float(h2));
    __nv_bfloat16 l3 = __float2bfloat16_rn(v.w - __bfloat162float(h3));
    oh.x = ((uint32_t)__bfloat16_as_ushort(h1) << 16) | __bfloat16_as_ushort(h0);
    oh.y = ((uint32_t)__bfloat16_as_ushort(h3) << 16) | __bfloat16_as_ushort(h2);
    ol.x = ((uint32_t)__bfloat16_as_ushort(l1) << 16) | __bfloat16_as_ushort(l0);
    ol.y = ((uint32_t)__bfloat16_as_ushort(l3) << 16) | __bfloat16_as_ushort(l2);
}

// ---------------------------------------------------------------------------
// Kernel A: convert x -> hi/lo bf16 (round-8 configuration).
// ---------------------------------------------------------------------------
__global__ __launch_bounds__(256) void convert_x_kernel(const float* __restrict__ x)
{
    const int i = blockIdx.x * 256 + threadIdx.x;   // float4 index
    float4 v = reinterpret_cast<const float4*>(x)[i];
    uint2 oh, ol;
    split4(v, oh, ol);
    reinterpret_cast<uint2*>(x_hi)[i] = oh;
    reinterpret_cast<uint2*>(x_lo)[i] = ol;
}

// ---------------------------------------------------------------------------
// Kernel B: convert stacked W -> hi/lo bf16.
// ---------------------------------------------------------------------------
__global__ __launch_bounds__(256) void convert_w_kernel(
    const float* __restrict__ Wq, const float* __restrict__ Wk,
    const float* __restrict__ Wv)
{
    const int row = blockIdx.x;
    const float* src = (row < 64) ? (Wq + (size_t)row * EMB)
                     : (row < 128) ? (Wk + (size_t)(row - 64) * EMB)
                                   : (Wv + (size_t)(row - 128) * EMB);
    const int i = threadIdx.x;
    float4 v = reinterpret_cast<const float4*>(src)[i];
    uint2 oh, ol;
    split4(v, oh, ol);
    reinterpret_cast<uint2*>(w_hi)[(size_t)row * (EMB / 4) + i] = oh;
    reinterpret_cast<uint2*>(w_lo)[(size_t)row * (EMB / 4) + i] = ol;
}

// ---------------------------------------------------------------------------
// Kernel C: QKV GEMM via mma.sync bf16 (3-term split) — round-8 config,
// all-cp.async staging from pre-converted x_hi/x_lo.
// grid 128, 256 threads (2 M x 4 N warps). Tile M=64, N=192, K chunks 64.
// ---------------------------------------------------------------------------
#define GPITCH 144
#define OFF_AH 0
#define OFF_AL 9216
#define OFF_BH 18432
#define OFF_BL 46080
#define GBUF   73728
#define GEMM_SMEM (2 * GBUF)
#define CHUNKS 16

__device__ __forceinline__ void qkv_stage_cp(uint32_t bufb, int c, int row0, int tid)
{
#pragma unroll
    for (int u = 0; u < 2; u++) {
        int idx = tid + u * 256;           // 0..511
        int r = idx >> 3, seg = idx & 7;
        uint32_t dst = r * GPITCH + seg * 16;
        cp16(bufb + OFF_AH + dst, &x_hi[(size_t)(row0 + r) * EMB + c * 64 + seg * 8]);
        cp16(bufb + OFF_AL + dst, &x_lo[(size_t)(row0 + r) * EMB + c * 64 + seg * 8]);
    }
#pragma unroll
    for (int u = 0; u < 6; u++) {
        int idx = tid + u * 256;           // 0..1535
        int r = idx >> 3, seg = idx & 7;
        uint32_t dst = r * GPITCH + seg * 16;
        cp16(bufb + OFF_BH + dst, &w_hi[(size_t)r * EMB + c * 64 + seg * 8]);
        cp16(bufb + OFF_BL + dst, &w_lo[(size_t)r * EMB + c * 64 + seg * 8]);
    }
}

__global__ __launch_bounds__(256) void qkv_gemm_kernel()
{
    extern __shared__ char smg[];
    const uint32_t smb = smem_u32(smg);
    const int tid  = threadIdx.x;
    const int lane = tid & 31;
    const int w    = tid >> 5;
    const int wm   = w & 1;
    const int wn   = w >> 1;
    const int row0 = blockIdx.x * 64;

    float acc[2][6][4];
#pragma unroll
    for (int mm = 0; mm < 2; mm++)
#pragma unroll
        for (int nn = 0; nn < 6; nn++)
#pragma unroll
            for (int q = 0; q < 4; q++) acc[mm][nn][q] = 0.f;

    const int g01 = (lane >> 3) & 1;
    const int g23 = (lane >> 4);
    const int tr  = lane & 7;

    qkv_stage_cp(smb, 0, row0, tid);
    CP_COMMIT();

    for (int c = 0; c < CHUNKS; c++) {
        const uint32_t bufb = smb + (c & 1) * GBUF;
        if (c < CHUNKS - 1) {
            qkv_stage_cp(smb + ((c + 1) & 1) * GBUF, c + 1, row0, tid);
            CP_COMMIT();
            CP_WAIT(1);
        } else {
            CP_WAIT(0);
        }
        __syncthreads();

#pragma unroll
        for (int pass = 0; pass < 3; pass++) {
            const uint32_t aoff = (pass == 2) ? OFF_AL : OFF_AH;
            const uint32_t boff = (pass == 1) ? OFF_BL : OFF_BH;
#pragma unroll
            for (int ks = 0; ks < 4; ks++) {
                uint32_t afr[2][4];
#pragma unroll
                for (int mm = 0; mm < 2; mm++) {
                    uint32_t addr = bufb + aoff
                        + (uint32_t)(wm * 32 + mm * 16 + g01 * 8 + tr) * GPITCH
                        + (uint32_t)(ks * 16 + g23 * 8) * 2;
                    ldsm4(afr[mm], addr);
                }
                uint32_t bfr[3][4];
#pragma unroll
                for (int ng = 0; ng < 3; ng++) {
                    uint32_t addr = bufb + boff
                        + (uint32_t)(wn * 48 + ng * 16 + g23 * 8 + tr) * GPITCH
                        + (uint32_t)(ks * 16 + g01 * 8) * 2;
                    ldsm4(bfr[ng], addr);
                }
#pragma unroll
                for (int mm = 0; mm < 2; mm++)
#pragma unroll
                    for (int nn = 0; nn < 6; nn++)
                        mma_bf16(acc[mm][nn], afr[mm], &bfr[nn >> 1][(nn & 1) * 2]);
            }
        }
        __syncthreads();
    }

    // epilogue
    const int mrow = lane >> 2;
    const int ncol = 2 * (lane & 3);
#pragma unroll
    for (int mm = 0; mm < 2; mm++) {
#pragma unroll
        for (int nn = 0; nn < 6; nn++) {
            const int n = wn * 48 + nn * 8 + ncol;
            const int m = row0 + wm * 32 + mm * 16 + mrow;
            const float* cvals = acc[mm][nn];
            if (n < 64) {
                g_qT[(size_t)n * MTOT + m]           = cvals[0];
                g_qT[(size_t)(n + 1) * MTOT + m]     = cvals[1];
                g_qT[(size_t)n * MTOT + m + 8]       = cvals[2];
                g_qT[(size_t)(n + 1) * MTOT + m + 8] = cvals[3];
            } else if (n < 128) {
                const int nk = n - 64;
                g_kT[(size_t)nk * MTOT + m]           = cvals[0];
                g_kT[(size_t)(nk + 1) * MTOT + m]     = cvals[1];
                g_kT[(size_t)nk * MTOT + m + 8]       = cvals[2];
                g_kT[(size_t)(nk + 1) * MTOT + m + 8] = cvals[3];
            } else {
                const int nv = n - 128;
                *reinterpret_cast<float2*>(&g_vs[(size_t)m * HD + nv]) =
                    make_float2(cvals[0], cvals[1]);
                *reinterpret_cast<float2*>(&g_vs[(size_t)(m + 8) * HD + nv]) =
                    make_float2(cvals[2], cvals[3]);
            }
        }
    }
}

// ---------------------------------------------------------------------------
// Kernel D: per-batch mean of V rows — parallel version (only change vs R8).
// ---------------------------------------------------------------------------
__global__ __launch_bounds__(256) void vmean1_kernel()
{
    const int b = blockIdx.x;
    const int c = blockIdx.y;                // 64-row chunk
    const int d = threadIdx.x & 63;
    const int sub = threadIdx.x >> 6;
    float s = 0.f;
    const int i0 = c * 64 + sub * 16;
#pragma unroll 4
    for (int i = i0; i < i0 + 16; i++)
        s += g_vs[((size_t)b * SEQ + i) * HD + d];
    __shared__ float red[256];
    red[threadIdx.x] = s;
    __syncthreads();
    if (sub == 0)
        g_vpart[(b * 32 + c) * HD + d] =
            red[d] + red[64 + d] + red[128 + d] + red[192 + d];
}

__global__ __launch_bounds__(256) void vmean2_kernel()
{
    const int b = blockIdx.x;
    const int d = threadIdx.x & 63;
    const int sub = threadIdx.x >> 6;
    float s = 0.f;
#pragma unroll
    for (int c = sub * 8; c < sub * 8 + 8; c++)
        s += g_vpart[(b * 32 + c) * HD + d];
    __shared__ float red[256];
    red[threadIdx.x] = s;
    __syncthreads();
    if (sub == 0)
        g_vmean[b * HD + d] =
            (red[d] + red[64 + d] + red[128 + d] + red[192 + d]) * (1.0f / SEQ);
}

// ---------------------------------------------------------------------------
// Kernel E: attention partials — round-8 configuration verbatim.
// Jobs: (batch, 64-row q-tile, <=512-key chunk) -> 80/batch, 320 total.
// ---------------------------------------------------------------------------
#define PQ2 68
#define PK2 132
#define PV2 68
#define PP2 68

#define A_QT 0
#define A_KT (A_QT + 64 * PQ2)
#define A_V  (A_KT + 64 * PK2)
#define A_PT (A_V + 128 * PV2)
#define ATTN_SMEM ((A_PT + 128 * PP2) * 4)

__global__ __launch_bounds__(256) void attn_partial_kernel(
    const int* __restrict__ pad)
{
    const int bid = blockIdx.x;
    const int b = bid / 80;
    const int rem = bid - b * 80;
    int jq, ch;
    if (rem < 8)       { jq = rem;                   ch = 0; }
    else if (rem < 24) { jq = 8 + ((rem - 8) >> 1);  ch = (rem - 8) & 1; }
    else if (rem < 48) { jq = 16 + (rem - 24) / 3;   ch = (rem - 24) % 3; }
    else               { jq = 24 + ((rem - 48) >> 2); ch = (rem - 48) & 3; }
    const int q0 = jq * 64;
    const int kstart = ch * 512;
    const int kmax = q0 + 64;
    const int kend = (kstart + 512 < kmax) ? kstart + 512 : kmax;
    const int nkt = (kend - kstart + 127) >> 7;

    const int tid  = threadIdx.x;
    const int lane = tid & 31;
    const int ty8  = (tid >> 5) * 8;

    extern __shared__ float smem[];
    float* sQt = smem + A_QT;
    float* sKt = smem + A_KT;
    float* sV  = smem + A_V;
    float* sPt = smem + A_PT;
    __shared__ int sPad[128];

#pragma unroll
    for (int u = 0; u < 4; u++) {
        int idx = tid + u * 256;
        int d = idx >> 4, f = (idx & 15) * 4;
        float4 v4 = *reinterpret_cast<const float4*>(
            &g_qT[(size_t)d * MTOT + b * SEQ + q0 + f]);
        *reinterpret_cast<float4*>(&sQt[d * PQ2 + f]) = v4;
    }

    float m[8], l[8];
    u64 o2[4][2];
#pragma unroll
    for (int r = 0; r < 8; r++) { m[r] = -3.0e38f; l[r] = 0.f; }
#pragma unroll
    for (int p = 0; p < 4; p++) { o2[p][0] = 0ULL; o2[p][1] = 0ULL; }

    for (int kt = 0; kt < nkt; kt++) {
        const int k0 = kstart + kt * 128;
        __syncthreads();

#pragma unroll
        for (int u = 0; u < 8; u++) {
            int idx = tid + u * 256;
            int d = idx >> 5, f = (idx & 31) * 4;
            float4 v4 = *reinterpret_cast<const float4*>(
                &g_kT[(size_t)d * MTOT + b * SEQ + k0 + f]);
            *reinterpret_cast<float4*>(&sKt[d * PK2 + f]) = v4;
        }
#pragma unroll
        for (int u = 0; u < 8; u++) {
            int idx = tid + u * 256;
            int r = idx >> 4, f = (idx & 15) * 4;
            float4 a = *reinterpret_cast<const float4*>(
                &g_vs[((size_t)b * SEQ + k0 + r) * HD + f]);
            *reinterpret_cast<float4*>(&sV[r * PV2 + f]) = a;
        }
        if (tid < 128) sPad[tid] = pad[b * SEQ + k0 + tid];
        __syncthreads();

        u64 s2[4][4];
#pragma unroll
        for (int p = 0; p < 4; p++)
#pragma unroll
            for (int i = 0; i < 4; i++) s2[p][i] = 0ULL;
#pragma unroll 8
        for (int d = 0; d < 64; d++) {
            ulonglong2 qA = *reinterpret_cast<const ulonglong2*>(&sQt[d * PQ2 + ty8]);
            ulonglong2 qB = *reinterpret_cast<const ulonglong2*>(&sQt[d * PQ2 + ty8 + 4]);
            float4 kv = *reinterpret_cast<const float4*>(&sKt[d * PK2 + lane * 4]);
            u64 k0s = splat2(kv.x), k1s = splat2(kv.y);
            u64 k2s = splat2(kv.z), k3s = splat2(kv.w);
            fma2(s2[0][0], qA.x, k0s); fma2(s2[0][1], qA.x, k1s);
            fma2(s2[0][2], qA.x, k2s); fma2(s2[0][3], qA.x, k3s);
            fma2(s2[1][0], qA.y, k0s); fma2(s2[1][1], qA.y, k1s);
            fma2(s2[1][2], qA.y, k2s); fma2(s2[1][3], qA.y, k3s);
            fma2(s2[2][0], qB.x, k0s); fma2(s2[2][1], qB.x, k1s);
            fma2(s2[2][2], qB.x, k2s); fma2(s2[2][3], qB.x, k3s);
            fma2(s2[3][0], qB.y, k0s); fma2(s2[3][1], qB.y, k1s);
            fma2(s2[3][2], qB.y, k2s); fma2(s2[3][3], qB.y, k3s);
        }

        float sv[8][4];
#pragma unroll
        for (int p = 0; p < 4; p++)
#pragma unroll
            for (int i = 0; i < 4; i++)
                unpack2(s2[p][i], sv[2 * p][i], sv[2 * p + 1][i]);

        float p8[8][4], scl[8];
#pragma unroll
        for (int r = 0; r < 8; r++) {
            const int qi = q0 + ty8 + r;
#pragma unroll
            for (int i = 0; i < 4; i++) {
                const int kj = k0 + lane * 4 + i;
                const bool masked = (kj > qi) || (sPad[lane * 4 + i] == 0);
                sv[r][i] = (masked ? -1e9f : sv[r][i]) * 0.125f;
            }
            float tm = fmaxf(fmaxf(sv[r][0], sv[r][1]), fmaxf(sv[r][2], sv[r][3]));
            tm = fmaxf(tm, __shfl_xor_sync(0xffffffffu, tm, 1));
            tm = fmaxf(tm, __shfl_xor_sync(0xffffffffu, tm, 2));
            tm = fmaxf(tm, __shfl_xor_sync(0xffffffffu, tm, 4));
            tm = fmaxf(tm, __shfl_xor_sync(0xffffffffu, tm, 8));
            tm = fmaxf(tm, __shfl_xor_sync(0xffffffffu, tm, 16));
            const float mnew = fmaxf(m[r], tm);
            scl[r] = __expf(m[r] - mnew);
            float tl = 0.f;
#pragma unroll
            for (int i = 0; i < 4; i++) { p8[r][i] = __expf(sv[r][i] - mnew); tl += p8[r][i]; }
            tl += __shfl_xor_sync(0xffffffffu, tl, 1);
            tl += __shfl_xor_sync(0xffffffffu, tl, 2);
            tl += __shfl_xor_sync(0xffffffffu, tl, 4);
            tl += __shfl_xor_sync(0xffffffffu, tl, 8);
            tl += __shfl_xor_sync(0xffffffffu, tl, 16);
            l[r] = l[r] * scl[r] + tl;
            m[r] = mnew;
        }
#pragma unroll
        for (int p = 0; p < 4; p++) {
            u64 sp = pack2(scl[2 * p], scl[2 * p + 1]);
            mul2(o2[p][0], sp);
            mul2(o2[p][1], sp);
        }
#pragma unroll
        for (int i = 0; i < 4; i++) {
            const int key = lane * 4 + i;
            *reinterpret_cast<float4*>(&sPt[key * PP2 + ty8]) =
                make_float4(p8[0][i], p8[1][i], p8[2][i], p8[3][i]);
            *reinterpret_cast<float4*>(&sPt[key * PP2 + ty8 + 4]) =
                make_float4(p8[4][i], p8[5][i], p8[6][i], p8[7][i]);
        }
        __syncthreads();

#pragma unroll 8
        for (int j = 0; j < 128; j++) {
            ulonglong2 pA = *reinterpret_cast<const ulonglong2*>(&sPt[j * PP2 + ty8]);
            ulonglong2 pB = *reinterpret_cast<const ulonglong2*>(&sPt[j * PP2 + ty8 + 4]);
            float2 v2 = *reinterpret_cast<const float2*>(&sV[j * PV2 + lane * 2]);
            u64 v0 = splat2(v2.x), v1 = splat2(v2.y);
            fma2(o2[0][0], pA.x, v0); fma2(o2[0][1], pA.x, v1);
            fma2(o2[1][0], pA.y, v0); fma2(o2[1][1], pA.y, v1);
            fma2(o2[2][0], pB.x, v0); fma2(o2[2][1], pB.x, v1);
            fma2(o2[3][0], pB.y, v0); fma2(o2[3][1], pB.y, v1);
        }
    }

    if (lane == 0) {
#pragma unroll
        for (int r = 0; r < 8; r++) {
            g_pm[bid * 64 + ty8 + r] = m[r];
            g_pl[bid * 64 + ty8 + r] = l[r];
        }
    }
#pragma unroll
    for (int p = 0; p < 4; p++) {
        float aLo, aHi, bLo, bHi;
        unpack2(o2[p][0], aLo, aHi);
        unpack2(o2[p][1], bLo, bHi);
        *reinterpret_cast<float2*>(
            &g_po[(size_t)bid * 4096 + (ty8 + 2 * p) * 64 + lane * 2]) =
            make_float2(aLo, bLo);
        *reinterpret_cast<float2*>(
            &g_po[(size_t)bid * 4096 + (ty8 + 2 * p + 1) * 64 + lane * 2]) =
            make_float2(aHi, bHi);
    }
}

// ---------------------------------------------------------------------------
// Kernel F: merge partials (round-8 version).
// ---------------------------------------------------------------------------
__global__ __launch_bounds__(256) void attn_merge_kernel(float* __restrict__ out)
{
    const int b  = blockIdx.x >> 5;
    const int jq = blockIdx.x & 31;
    int off;
    if (jq < 8)       off = jq;
    else if (jq < 16) off = 8 + 2 * (jq - 8);
    else if (jq < 24) off = 24 + 3 * (jq - 16);
    else              off = 48 + 4 * (jq - 24);
    const int nch = (jq >> 3) + 1;
    const int jbase = b * 80 + off;
    const int q0 = jq * 64;

    const int d  = threadIdx.x & 63;
    const int r0 = threadIdx.x >> 6;

    for (int rr = 0; rr < 16; rr++) {
        const int row = r0 + rr * 4;
        float M = -3.0e38f;
        float mi[5], li[5];
#pragma unroll 5
        for (int i = 0; i < 5; i++) {
            if (i < nch) {
                mi[i] = g_pm[(jbase + i) * 64 + row];
                li[i] = g_pl[(jbase + i) * 64 + row];
                M = fmaxf(M, mi[i]);
            }
        }
        float L = 0.f, O = 0.f;
#pragma unroll 5
        for (int i = 0; i < 5; i++) {
            if (i < nch) {
                float w = __expf(mi[i] - M);
                L += li[i] * w;
                O += g_po[(size_t)(jbase + i) * 4096 + row * 64 + d] * w;
            }
        }
        float res = (M <= -1.0e8f) ? g_vmean[b * HD + d] : O / L;
        out[((size_t)b * SEQ + q0 + row) * HD + d] = res;
    }
}

// ---------------------------------------------------------------------------
extern "C" void kernel_launch(void* const* d_in, const int* in_sizes, int n_in,
                              void* d_out, int out_size)
{
    const float* x   = (const float*)d_in[0];
    const int*   pad = (const int*)  d_in[1];
    const float* Wq  = (const float*)d_in[2];
    const float* Wk  = (const float*)d_in[3];
    const float* Wv  = (const float*)d_in[4];
    float* out = (float*)d_out;

    cudaFuncSetAttribute(qkv_gemm_kernel,
                         cudaFuncAttributeMaxDynamicSharedMemorySize, GEMM_SMEM);
    cudaFuncSetAttribute(attn_partial_kernel,
                         cudaFuncAttributeMaxDynamicSharedMemorySize, ATTN_SMEM);

    convert_x_kernel<<<(MTOT * EMB / 4) / 256, 256>>>(x);
    convert_w_kernel<<<192, 256>>>(Wq, Wk, Wv);
    qkv_gemm_kernel<<<128, 256, GEMM_SMEM>>>();
    vmean1_kernel<<<dim3(BSZ, 32), 256>>>();
    vmean2_kernel<<<BSZ, 256>>>();
    attn_partial_kernel<<<NJOBS, 256, ATTN_SMEM>>>(pad);
    attn_merge_kernel<<<128, 256>>>(out);
}

// round 14
// speedup vs baseline: 1.5447x; 1.0281x over previous
#include <cuda_runtime.h>
#include <cuda_bf16.h>
#include <cstdint>

#define BSZ 4
#define SEQ 2048
#define EMB 1024
#define HD  64
#define MTOT (BSZ * SEQ)

// bf16 split operands
__device__ __nv_bfloat16 x_hi[MTOT * EMB];
__device__ __nv_bfloat16 x_lo[MTOT * EMB];
__device__ __nv_bfloat16 w_hi[192 * EMB];
__device__ __nv_bfloat16 w_lo[192 * EMB];
// projection outputs: Q,K transposed [dim][global row], V row-major
__device__ float g_qT[HD * MTOT];
__device__ float g_kT[HD * MTOT];
__device__ float g_vs[MTOT * HD];
// vmean
__device__ float g_vpart[BSZ * 32 * HD];
__device__ float g_vmean[BSZ * HD];
// attention split-key partials: 320 jobs (80 per batch, 512-key chunks)
#define NJOBS 320
__device__ float g_pm[NJOBS * 64];
__device__ float g_pl[NJOBS * 64];
__device__ float g_po[NJOBS * 64 * 64];

typedef unsigned long long u64;

__device__ __forceinline__ u64 splat2(float x) {
    u64 r; asm("mov.b64 %0, {%1, %1};" : "=l"(r) : "f"(x)); return r;
}
__device__ __forceinline__ u64 pack2(float lo, float hi) {
    u64 r; asm("mov.b64 %0, {%1, %2};" : "=l"(r) : "f"(lo), "f"(hi)); return r;
}
__device__ __forceinline__ void fma2(u64& d, u64 a, u64 b) {
    asm("fma.rn.f32x2 %0, %1, %2, %0;" : "+l"(d) : "l"(a), "l"(b));
}
__device__ __forceinline__ void mul2(u64& d, u64 s) {
    asm("mul.rn.f32x2 %0, %0, %1;" : "+l"(d) : "l"(s));
}
__device__ __forceinline__ void unpack2(u64 v, float& lo, float& hi) {
    asm("mov.b64 {%0, %1}, %2;" : "=f"(lo), "=f"(hi) : "l"(v));
}
__device__ __forceinline__ uint32_t smem_u32(const void* p) {
    uint32_t a;
    asm("{ .reg .u64 t; cvta.to.shared.u64 t, %1; cvt.u32.u64 %0, t; }"
        : "=r"(a) : "l"(p));
    return a;
}

// ---- portable tensor-core helpers ----------------------------------------
__device__ __forceinline__ void mma_bf16(float* d, const uint32_t* a,
                                         const uint32_t* b) {
    asm volatile(
        "mma.sync.aligned.m16n8k16.row.col.f32.bf16.bf16.f32 "
        "{%0,%1,%2,%3}, {%4,%5,%6,%7}, {%8,%9}, {%0,%1,%2,%3};"
        : "+f"(d[0]), "+f"(d[1]), "+f"(d[2]), "+f"(d[3])
        : "r"(a[0]), "r"(a[1]), "r"(a[2]), "r"(a[3]), "r"(b[0]), "r"(b[1]));
}
__device__ __forceinline__ void ldsm4(uint32_t* r, uint32_t addr) {
    asm volatile("ldmatrix.sync.aligned.m8n8.x4.shared.b16 {%0,%1,%2,%3}, [%4];"
                 : "=r"(r[0]), "=r"(r[1]), "=r"(r[2]), "=r"(r[3]) : "r"(addr));
}
__device__ __forceinline__ void cp16(uint32_t smaddr, const void* g) {
    asm volatile("cp.async.ca.shared.global [%0], [%1], 16;"
                 :: "r"(smaddr), "l"(g));
}
#define CP_COMMIT()  asm volatile("cp.async.commit_group;" ::: "memory")
#define CP_WAIT(n)   asm volatile("cp.async.wait_group %0;" :: "n"(n) : "memory")

// ---- bf16 hi/lo split of a float4 ----------------------------------------
__device__ __forceinline__ void split4(float4 v, uint2& oh, uint2& ol) {
    __nv_bfloat16 h0 = __float2bfloat16_rn(v.x);
    __nv_bfloat16 h1 = __float2bfloat16_rn(v.y);
    __nv_bfloat16 h2 = __float2bfloat16_rn(v.z);
    __nv_bfloat16 h3 = __float2bfloat16_rn(v.w);
    __nv_bfloat16 l0 = __float2bfloat16_rn(v.x - __bfloat162float(h0));
    __nv_bfloat16 l1 = __float2bfloat16_rn(v.y - __bfloat162float(h1));
    __nv_bfloat16 l2 = __float2bfloat16_rn(v.z - __bfloat162float(h2));
    __nv_bfloat16 l3 = __float2bfloat16_rn(v.w - __bfloat162float(h3));
    oh.x = ((uint32_t)__bfloat16_as_ushort(h1) << 16) | __bfloat16_as_ushort(h0);
    oh.y = ((uint32_t)__bfloat16_as_ushort(h3) << 16) | __bfloat16_as_ushort(h2);
    ol.x = ((uint32_t)__bfloat16_as_ushort(l1) << 16) | __bfloat16_as_ushort(l0);
    ol.y = ((uint32_t)__bfloat16_as_ushort(l3) << 16) | __bfloat16_as_ushort(l2);
}

// ---------------------------------------------------------------------------
// Kernel A: convert x -> hi/lo bf16.
// ---------------------------------------------------------------------------
__global__ __launch_bounds__(256) void convert_x_kernel(const float* __restrict__ x)
{
    const int i = blockIdx.x * 256 + threadIdx.x;   // float4 index
    float4 v = reinterpret_cast<const float4*>(x)[i];
    uint2 oh, ol;
    split4(v, oh, ol);
    reinterpret_cast<uint2*>(x_hi)[i] = oh;
    reinterpret_cast<uint2*>(x_lo)[i] = ol;
}

// ---------------------------------------------------------------------------
// Kernel B: convert stacked W -> hi/lo bf16.
// ---------------------------------------------------------------------------
__global__ __launch_bounds__(256) void convert_w_kernel(
    const float* __restrict__ Wq, const float* __restrict__ Wk,
    const float* __restrict__ Wv)
{
    const int row = blockIdx.x;
    const float* src = (row < 64) ? (Wq + (size_t)row * EMB)
                     : (row < 128) ? (Wk + (size_t)(row - 64) * EMB)
                                   : (Wv + (size_t)(row - 128) * EMB);
    const int i = threadIdx.x;
    float4 v = reinterpret_cast<const float4*>(src)[i];
    uint2 oh, ol;
    split4(v, oh, ol);
    reinterpret_cast<uint2*>(w_hi)[(size_t)row * (EMB / 4) + i] = oh;
    reinterpret_cast<uint2*>(w_lo)[(size_t)row * (EMB / 4) + i] = ol;
}

// ---------------------------------------------------------------------------
// Kernel C: QKV GEMM via mma.sync bf16 (3-term split) — round-8 config.
// ---------------------------------------------------------------------------
#define GPITCH 144
#define OFF_AH 0
#define OFF_AL 9216
#define OFF_BH 18432
#define OFF_BL 46080
#define GBUF   73728
#define GEMM_SMEM (2 * GBUF)
#define CHUNKS 16

__device__ __forceinline__ void qkv_stage_cp(uint32_t bufb, int c, int row0, int tid)
{
#pragma unroll
    for (int u = 0; u < 2; u++) {
        int idx = tid + u * 256;
        int r = idx >> 3, seg = idx & 7;
        uint32_t dst = r * GPITCH + seg * 16;
        cp16(bufb + OFF_AH + dst, &x_hi[(size_t)(row0 + r) * EMB + c * 64 + seg * 8]);
        cp16(bufb + OFF_AL + dst, &x_lo[(size_t)(row0 + r) * EMB + c * 64 + seg * 8]);
    }
#pragma unroll
    for (int u = 0; u < 6; u++) {
        int idx = tid + u * 256;
        int r = idx >> 3, seg = idx & 7;
        uint32_t dst = r * GPITCH + seg * 16;
        cp16(bufb + OFF_BH + dst, &w_hi[(size_t)r * EMB + c * 64 + seg * 8]);
        cp16(bufb + OFF_BL + dst, &w_lo[(size_t)r * EMB + c * 64 + seg * 8]);
    }
}

__global__ __launch_bounds__(256) void qkv_gemm_kernel()
{
    extern __shared__ char smg[];
    const uint32_t smb = smem_u32(smg);
    const int tid  = threadIdx.x;
    const int lane = tid & 31;
    const int w    = tid >> 5;
    const int wm   = w & 1;
    const int wn   = w >> 1;
    const int row0 = blockIdx.x * 64;

    float acc[2][6][4];
#pragma unroll
    for (int mm = 0; mm < 2; mm++)
#pragma unroll
        for (int nn = 0; nn < 6; nn++)
#pragma unroll
            for (int q = 0; q < 4; q++) acc[mm][nn][q] = 0.f;

    const int g01 = (lane >> 3) & 1;
    const int g23 = (lane >> 4);
    const int tr  = lane & 7;

    qkv_stage_cp(smb, 0, row0, tid);
    CP_COMMIT();

    for (int c = 0; c < CHUNKS; c++) {
        const uint32_t bufb = smb + (c & 1) * GBUF;
        if (c < CHUNKS - 1) {
            qkv_stage_cp(smb + ((c + 1) & 1) * GBUF, c + 1, row0, tid);
            CP_COMMIT();
            CP_WAIT(1);
        } else {
            CP_WAIT(0);
        }
        __syncthreads();

#pragma unroll
        for (int pass = 0; pass < 3; pass++) {
            const uint32_t aoff = (pass == 2) ? OFF_AL : OFF_AH;
            const uint32_t boff = (pass == 1) ? OFF_BL : OFF_BH;
#pragma unroll
            for (int ks = 0; ks < 4; ks++) {
                uint32_t afr[2][4];
#pragma unroll
                for (int mm = 0; mm < 2; mm++) {
                    uint32_t addr = bufb + aoff
                        + (uint32_t)(wm * 32 + mm * 16 + g01 * 8 + tr) * GPITCH
                        + (uint32_t)(ks * 16 + g23 * 8) * 2;
                    ldsm4(afr[mm], addr);
                }
                uint32_t bfr[3][4];
#pragma unroll
                for (int ng = 0; ng < 3; ng++) {
                    uint32_t addr = bufb + boff
                        + (uint32_t)(wn * 48 + ng * 16 + g23 * 8 + tr) * GPITCH
                        + (uint32_t)(ks * 16 + g01 * 8) * 2;
                    ldsm4(bfr[ng], addr);
                }
#pragma unroll
                for (int mm = 0; mm < 2; mm++)
#pragma unroll
                    for (int nn = 0; nn < 6; nn++)
                        mma_bf16(acc[mm][nn], afr[mm], &bfr[nn >> 1][(nn & 1) * 2]);
            }
        }
        __syncthreads();
    }

    const int mrow = lane >> 2;
    const int ncol = 2 * (lane & 3);
#pragma unroll
    for (int mm = 0; mm < 2; mm++) {
#pragma unroll
        for (int nn = 0; nn < 6; nn++) {
            const int n = wn * 48 + nn * 8 + ncol;
            const int m = row0 + wm * 32 + mm * 16 + mrow;
            const float* cvals = acc[mm][nn];
            if (n < 64) {
                g_qT[(size_t)n * MTOT + m]           = cvals[0];
                g_qT[(size_t)(n + 1) * MTOT + m]     = cvals[1];
                g_qT[(size_t)n * MTOT + m + 8]       = cvals[2];
                g_qT[(size_t)(n + 1) * MTOT + m + 8] = cvals[3];
            } else if (n < 128) {
                const int nk = n - 64;
                g_kT[(size_t)nk * MTOT + m]           = cvals[0];
                g_kT[(size_t)(nk + 1) * MTOT + m]     = cvals[1];
                g_kT[(size_t)nk * MTOT + m + 8]       = cvals[2];
                g_kT[(size_t)(nk + 1) * MTOT + m + 8] = cvals[3];
            } else {
                const int nv = n - 128;
                *reinterpret_cast<float2*>(&g_vs[(size_t)m * HD + nv]) =
                    make_float2(cvals[0], cvals[1]);
                *reinterpret_cast<float2*>(&g_vs[(size_t)(m + 8) * HD + nv]) =
                    make_float2(cvals[2], cvals[3]);
            }
        }
    }
}

// ---------------------------------------------------------------------------
// Kernel D: per-batch mean of V rows (parallel).
// ---------------------------------------------------------------------------
__global__ __launch_bounds__(256) void vmean1_kernel()
{
    const int b = blockIdx.x;
    const int c = blockIdx.y;
    const int d = threadIdx.x & 63;
    const int sub = threadIdx.x >> 6;
    float s = 0.f;
    const int i0 = c * 64 + sub * 16;
#pragma unroll 4
    for (int i = i0; i < i0 + 16; i++)
        s += g_vs[((size_t)b * SEQ + i) * HD + d];
    __shared__ float red[256];
    red[threadIdx.x] = s;
    __syncthreads();
    if (sub == 0)
        g_vpart[(b * 32 + c) * HD + d] =
            red[d] + red[64 + d] + red[128 + d] + red[192 + d];
}

__global__ __launch_bounds__(256) void vmean2_kernel()
{
    const int b = blockIdx.x;
    const int d = threadIdx.x & 63;
    const int sub = threadIdx.x >> 6;
    float s = 0.f;
#pragma unroll
    for (int c = sub * 8; c < sub * 8 + 8; c++)
        s += g_vpart[(b * 32 + c) * HD + d];
    __shared__ float red[256];
    red[threadIdx.x] = s;
    __syncthreads();
    if (sub == 0)
        g_vmean[b * HD + d] =
            (red[d] + red[64 + d] + red[128 + d] + red[192 + d]) * (1.0f / SEQ);
}

// ---------------------------------------------------------------------------
// Kernel E: attention partials — R8 config + double-buffered cp.async K/V
// staging (overlap next tile's loads with current tile's compute).
// smem layout (floats): Q 64*68 | K0 64*132 | K1 | V0 128*68 | V1 | P 128*68
// total 47360 floats = 185 KB, 1 block/SM.
// ---------------------------------------------------------------------------
#define PQ2 68
#define PK2 132
#define PV2 68
#define PP2 68

#define A_QT 0
#define A_K0 (A_QT + 64 * PQ2)
#define A_K1 (A_K0 + 64 * PK2)
#define A_V0 (A_K1 + 64 * PK2)
#define A_V1 (A_V0 + 128 * PV2)
#define A_PT (A_V1 + 128 * PV2)
#define ATTN_SMEM ((A_PT + 128 * PP2) * 4)

__device__ __forceinline__ void attn_stage(uint32_t smb, int buf, int b, int k0,
                                           int tid, const int* __restrict__ pad,
                                           int* sPadBuf)
{
    const uint32_t kbase = smb + (A_K0 + buf * 64 * PK2) * 4;
    const uint32_t vbase = smb + (A_V0 + buf * 128 * PV2) * 4;
#pragma unroll
    for (int u = 0; u < 8; u++) {
        int idx = tid + u * 256;           // 0..2047
        int d = idx >> 5, f = (idx & 31) * 4;
        cp16(kbase + (uint32_t)(d * PK2 + f) * 4,
             &g_kT[(size_t)d * MTOT + b * SEQ + k0 + f]);
    }
#pragma unroll
    for (int u = 0; u < 8; u++) {
        int idx = tid + u * 256;
        int r = idx >> 4, f = (idx & 15) * 4;
        cp16(vbase + (uint32_t)(r * PV2 + f) * 4,
             &g_vs[((size_t)b * SEQ + k0 + r) * HD + f]);
    }
    if (tid < 128) sPadBuf[tid] = pad[b * SEQ + k0 + tid];
}

__global__ __launch_bounds__(256) void attn_partial_kernel(
    const int* __restrict__ pad)
{
    const int bid = blockIdx.x;
    const int b = bid / 80;
    const int rem = bid - b * 80;
    int jq, ch;
    if (rem < 8)       { jq = rem;                   ch = 0; }
    else if (rem < 24) { jq = 8 + ((rem - 8) >> 1);  ch = (rem - 8) & 1; }
    else if (rem < 48) { jq = 16 + (rem - 24) / 3;   ch = (rem - 24) % 3; }
    else               { jq = 24 + ((rem - 48) >> 2); ch = (rem - 48) & 3; }
    const int q0 = jq * 64;
    const int kstart = ch * 512;
    const int kmax = q0 + 64;
    const int kend = (kstart + 512 < kmax) ? kstart + 512 : kmax;
    const int nkt = (kend - kstart + 127) >> 7;

    const int tid  = threadIdx.x;
    const int lane = tid & 31;
    const int ty8  = (tid >> 5) * 8;

    extern __shared__ float smem[];
    const uint32_t smb = smem_u32(smem);
    float* sQt = smem + A_QT;
    float* sPt = smem + A_PT;
    __shared__ int sPad[2][128];

    // stage Q (regular loads; once per job)
#pragma unroll
    for (int u = 0; u < 4; u++) {
        int idx = tid + u * 256;
        int d = idx >> 4, f = (idx & 15) * 4;
        float4 v4 = *reinterpret_cast<const float4*>(
            &g_qT[(size_t)d * MTOT + b * SEQ + q0 + f]);
        *reinterpret_cast<float4*>(&sQt[d * PQ2 + f]) = v4;
    }

    float m[8], l[8];
    u64 o2[4][2];
#pragma unroll
    for (int r = 0; r < 8; r++) { m[r] = -3.0e38f; l[r] = 0.f; }
#pragma unroll
    for (int p = 0; p < 4; p++) { o2[p][0] = 0ULL; o2[p][1] = 0ULL; }

    // prologue: stage tile 0 into buffer 0
    attn_stage(smb, 0, b, kstart, tid, pad, sPad[0]);
    CP_COMMIT();

    for (int kt = 0; kt < nkt; kt++) {
        const int cb = kt & 1;
        const int k0 = kstart + kt * 128;
        if (kt < nkt - 1) {
            attn_stage(smb, cb ^ 1, b, k0 + 128, tid, pad, sPad[cb ^ 1]);
            CP_COMMIT();
            CP_WAIT(1);
        } else {
            CP_WAIT(0);
        }
        __syncthreads();   // tile kt data visible to all

        float* sKt = smem + A_K0 + cb * 64 * PK2;
        float* sV  = smem + A_V0 + cb * 128 * PV2;
        const int* sPadC = sPad[cb];

        // S = Q K^T
        u64 s2[4][4];
#pragma unroll
        for (int p = 0; p < 4; p++)
#pragma unroll
            for (int i = 0; i < 4; i++) s2[p][i] = 0ULL;
#pragma unroll 8
        for (int d = 0; d < 64; d++) {
            ulonglong2 qA = *reinterpret_cast<const ulonglong2*>(&sQt[d * PQ2 + ty8]);
            ulonglong2 qB = *reinterpret_cast<const ulonglong2*>(&sQt[d * PQ2 + ty8 + 4]);
            float4 kv = *reinterpret_cast<const float4*>(&sKt[d * PK2 + lane * 4]);
            u64 k0s = splat2(kv.x), k1s = splat2(kv.y);
            u64 k2s = splat2(kv.z), k3s = splat2(kv.w);
            fma2(s2[0][0], qA.x, k0s); fma2(s2[0][1], qA.x, k1s);
            fma2(s2[0][2], qA.x, k2s); fma2(s2[0][3], qA.x, k3s);
            fma2(s2[1][0], qA.y, k0s); fma2(s2[1][1], qA.y, k1s);
            fma2(s2[1][2], qA.y, k2s); fma2(s2[1][3], qA.y, k3s);
            fma2(s2[2][0], qB.x, k0s); fma2(s2[2][1], qB.x, k1s);
            fma2(s2[2][2], qB.x, k2s); fma2(s2[2][3], qB.x, k3s);
            fma2(s2[3][0], qB.y, k0s); fma2(s2[3][1], qB.y, k1s);
            fma2(s2[3][2], qB.y, k2s); fma2(s2[3][3], qB.y, k3s);
        }

        float sv[8][4];
#pragma unroll
        for (int p = 0; p < 4; p++)
#pragma unroll
            for (int i = 0; i < 4; i++)
                unpack2(s2[p][i], sv[2 * p][i], sv[2 * p + 1][i]);

        float p8[8][4], scl[8];
#pragma unroll
        for (int r = 0; r < 8; r++) {
            const int qi = q0 + ty8 + r;
#pragma unroll
            for (int i = 0; i < 4; i++) {
                const int kj = k0 + lane * 4 + i;
                const bool masked = (kj > qi) || (sPadC[lane * 4 + i] == 0);
                sv[r][i] = (masked ? -1e9f : sv[r][i]) * 0.125f;
            }
            float tm = fmaxf(fmaxf(sv[r][0], sv[r][1]), fmaxf(sv[r][2], sv[r][3]));
            tm = fmaxf(tm, __shfl_xor_sync(0xffffffffu, tm, 1));
            tm = fmaxf(tm, __shfl_xor_sync(0xffffffffu, tm, 2));
            tm = fmaxf(tm, __shfl_xor_sync(0xffffffffu, tm, 4));
            tm = fmaxf(tm, __shfl_xor_sync(0xffffffffu, tm, 8));
            tm = fmaxf(tm, __shfl_xor_sync(0xffffffffu, tm, 16));
            const float mnew = fmaxf(m[r], tm);
            scl[r] = __expf(m[r] - mnew);
            float tl = 0.f;
#pragma unroll
            for (int i = 0; i < 4; i++) { p8[r][i] = __expf(sv[r][i] - mnew); tl += p8[r][i]; }
            tl += __shfl_xor_sync(0xffffffffu, tl, 1);
            tl += __shfl_xor_sync(0xffffffffu, tl, 2);
            tl += __shfl_xor_sync(0xffffffffu, tl, 4);
            tl += __shfl_xor_sync(0xffffffffu, tl, 8);
            tl += __shfl_xor_sync(0xffffffffu, tl, 16);
            l[r] = l[r] * scl[r] + tl;
            m[r] = mnew;
        }
#pragma unroll
        for (int p = 0; p < 4; p++) {
            u64 sp = pack2(scl[2 * p], scl[2 * p + 1]);
            mul2(o2[p][0], sp);
            mul2(o2[p][1], sp);
        }
#pragma unroll
        for (int i = 0; i < 4; i++) {
            const int key = lane * 4 + i;
            *reinterpret_cast<float4*>(&sPt[key * PP2 + ty8]) =
                make_float4(p8[0][i], p8[1][i], p8[2][i], p8[3][i]);
            *reinterpret_cast<float4*>(&sPt[key * PP2 + ty8 + 4]) =
                make_float4(p8[4][i], p8[5][i], p8[6][i], p8[7][i]);
        }
        __syncthreads();   // P visible

        // O += P V
#pragma unroll 8
        for (int j = 0; j < 128; j++) {
            ulonglong2 pA = *reinterpret_cast<const ulonglong2*>(&sPt[j * PP2 + ty8]);
            ulonglong2 pB = *reinterpret_cast<const ulonglong2*>(&sPt[j * PP2 + ty8 + 4]);
            float2 v2 = *reinterpret_cast<const float2*>(&sV[j * PV2 + lane * 2]);
            u64 v0 = splat2(v2.x), v1 = splat2(v2.y);
            fma2(o2[0][0], pA.x, v0); fma2(o2[0][1], pA.x, v1);
            fma2(o2[1][0], pA.y, v0); fma2(o2[1][1], pA.y, v1);
            fma2(o2[2][0], pB.x, v0); fma2(o2[2][1], pB.x, v1);
            fma2(o2[3][0], pB.y, v0); fma2(o2[3][1], pB.y, v1);
        }
        __syncthreads();   // buffer recycle guard (next iter writes buf cb)
    }

    if (lane == 0) {
#pragma unroll
        for (int r = 0; r < 8; r++) {
            g_pm[bid * 64 + ty8 + r] = m[r];
            g_pl[bid * 64 + ty8 + r] = l[r];
        }
    }
#pragma unroll
    for (int p = 0; p < 4; p++) {
        float aLo, aHi, bLo, bHi;
        unpack2(o2[p][0], aLo, aHi);
        unpack2(o2[p][1], bLo, bHi);
        *reinterpret_cast<float2*>(
            &g_po[(size_t)bid * 4096 + (ty8 + 2 * p) * 64 + lane * 2]) =
            make_float2(aLo, bLo);
        *reinterpret_cast<float2*>(
            &g_po[(size_t)bid * 4096 + (ty8 + 2 * p + 1) * 64 + lane * 2]) =
            make_float2(aHi, bHi);
    }
}

// ---------------------------------------------------------------------------
// Kernel F: merge partials.
// ---------------------------------------------------------------------------
__global__ __launch_bounds__(256) void attn_merge_kernel(float* __restrict__ out)
{
    const int b  = blockIdx.x >> 5;
    const int jq = blockIdx.x & 31;
    int off;
    if (jq < 8)       off = jq;
    else if (jq < 16) off = 8 + 2 * (jq - 8);
    else if (jq < 24) off = 24 + 3 * (jq - 16);
    else              off = 48 + 4 * (jq - 24);
    const int nch = (jq >> 3) + 1;
    const int jbase = b * 80 + off;
    const int q0 = jq * 64;

    const int d  = threadIdx.x & 63;
    const int r0 = threadIdx.x >> 6;

    for (int rr = 0; rr < 16; rr++) {
        const int row = r0 + rr * 4;
        float M = -3.0e38f;
        float mi[5], li[5];
#pragma unroll 5
        for (int i = 0; i < 5; i++) {
            if (i < nch) {
                mi[i] = g_pm[(jbase + i) * 64 + row];
                li[i] = g_pl[(jbase + i) * 64 + row];
                M = fmaxf(M, mi[i]);
            }
        }
        float L = 0.f, O = 0.f;
#pragma unroll 5
        for (int i = 0; i < 5; i++) {
            if (i < nch) {
                float w = __expf(mi[i] - M);
                L += li[i] * w;
                O += g_po[(size_t)(jbase + i) * 4096 + row * 64 + d] * w;
            }
        }
        float res = (M <= -1.0e8f) ? g_vmean[b * HD + d] : O / L;
        out[((size_t)b * SEQ + q0 + row) * HD + d] = res;
    }
}

// ---------------------------------------------------------------------------
extern "C" void kernel_launch(void* const* d_in, const int* in_sizes, int n_in,
                              void* d_out, int out_size)
{
    const float* x   = (const float*)d_in[0];
    const int*   pad = (const int*)  d_in[1];
    const float* Wq  = (const float*)d_in[2];
    const float* Wk  = (const float*)d_in[3];
    const float* Wv  = (const float*)d_in[4];
    float* out = (float*)d_out;

    cudaFuncSetAttribute(qkv_gemm_kernel,
                         cudaFuncAttributeMaxDynamicSharedMemorySize, GEMM_SMEM);
    cudaFuncSetAttribute(attn_partial_kernel,
                         cudaFuncAttributeMaxDynamicSharedMemorySize, ATTN_SMEM);

    convert_x_kernel<<<(MTOT * EMB / 4) / 256, 256>>>(x);
    convert_w_kernel<<<192, 256>>>(Wq, Wk, Wv);
    qkv_gemm_kernel<<<128, 256, GEMM_SMEM>>>();
    vmean1_kernel<<<dim3(BSZ, 32), 256>>>();
    vmean2_kernel<<<BSZ, 256>>>();
    attn_partial_kernel<<<NJOBS, 256, ATTN_SMEM>>>(pad);
    attn_merge_kernel<<<128, 256>>>(out);
}

// round 15
// speedup vs baseline: 1.6198x; 1.0486x over previous
#include <cuda_runtime.h>
#include <cuda_bf16.h>
#include <cstdint>

#define BSZ 4
#define SEQ 2048
#define EMB 1024
#define HD  64
#define MTOT (BSZ * SEQ)

// bf16 split operands
__device__ __nv_bfloat16 x_hi[MTOT * EMB];
__device__ __nv_bfloat16 x_lo[MTOT * EMB];
__device__ __nv_bfloat16 w_hi[192 * EMB];
__device__ __nv_bfloat16 w_lo[192 * EMB];
// projection outputs: Q,K bf16 hi/lo row-major [row][64]; V fp32 row-major
__device__ __nv_bfloat16 q_hi[MTOT * HD];
__device__ __nv_bfloat16 q_lo[MTOT * HD];
__device__ __nv_bfloat16 k_hi[MTOT * HD];
__device__ __nv_bfloat16 k_lo[MTOT * HD];
__device__ float g_vs[MTOT * HD];
// vmean
__device__ float g_vpart[BSZ * 32 * HD];
__device__ float g_vmean[BSZ * HD];
// attention split-key partials: 320 jobs (80 per batch, 512-key chunks)
#define NJOBS 320
__device__ float g_pm[NJOBS * 64];
__device__ float g_pl[NJOBS * 64];
__device__ float g_po[NJOBS * 64 * 64];

typedef unsigned long long u64;

__device__ __forceinline__ u64 splat2(float x) {
    u64 r; asm("mov.b64 %0, {%1, %1};" : "=l"(r) : "f"(x)); return r;
}
__device__ __forceinline__ u64 pack2(float lo, float hi) {
    u64 r; asm("mov.b64 %0, {%1, %2};" : "=l"(r) : "f"(lo), "f"(hi)); return r;
}
__device__ __forceinline__ void fma2(u64& d, u64 a, u64 b) {
    asm("fma.rn.f32x2 %0, %1, %2, %0;" : "+l"(d) : "l"(a), "l"(b));
}
__device__ __forceinline__ void mul2(u64& d, u64 s) {
    asm("mul.rn.f32x2 %0, %0, %1;" : "+l"(d) : "l"(s));
}
__device__ __forceinline__ void unpack2(u64 v, float& lo, float& hi) {
    asm("mov.b64 {%0, %1}, %2;" : "=f"(lo), "=f"(hi) : "l"(v));
}
__device__ __forceinline__ uint32_t smem_u32(const void* p) {
    uint32_t a;
    asm("{ .reg .u64 t; cvta.to.shared.u64 t, %1; cvt.u32.u64 %0, t; }"
        : "=r"(a) : "l"(p));
    return a;
}

// ---- portable tensor-core helpers ----------------------------------------
__device__ __forceinline__ void mma_bf16(float* d, const uint32_t* a,
                                         const uint32_t* b) {
    asm volatile(
        "mma.sync.aligned.m16n8k16.row.col.f32.bf16.bf16.f32 "
        "{%0,%1,%2,%3}, {%4,%5,%6,%7}, {%8,%9}, {%0,%1,%2,%3};"
        : "+f"(d[0]), "+f"(d[1]), "+f"(d[2]), "+f"(d[3])
        : "r"(a[0]), "r"(a[1]), "r"(a[2]), "r"(a[3]), "r"(b[0]), "r"(b[1]));
}
__device__ __forceinline__ void ldsm4(uint32_t* r, uint32_t addr) {
    asm volatile("ldmatrix.sync.aligned.m8n8.x4.shared.b16 {%0,%1,%2,%3}, [%4];"
                 : "=r"(r[0]), "=r"(r[1]), "=r"(r[2]), "=r"(r[3]) : "r"(addr));
}
__device__ __forceinline__ void cp16(uint32_t smaddr, const void* g) {
    asm volatile("cp.async.ca.shared.global [%0], [%1], 16;"
                 :: "r"(smaddr), "l"(g));
}
#define CP_COMMIT()  asm volatile("cp.async.commit_group;" ::: "memory")
#define CP_WAIT(n)   asm volatile("cp.async.wait_group %0;" :: "n"(n) : "memory")

// ---- bf16 hi/lo split helpers ---------------------------------------------
__device__ __forceinline__ void split4(float4 v, uint2& oh, uint2& ol) {
    __nv_bfloat16 h0 = __float2bfloat16_rn(v.x);
    __nv_bfloat16 h1 = __float2bfloat16_rn(v.y);
    __nv_bfloat16 h2 = __float2bfloat16_rn(v.z);
    __nv_bfloat16 h3 = __float2bfloat16_rn(v.w);
    __nv_bfloat16 l0 = __float2bfloat16_rn(v.x - __bfloat162float(h0));
    __nv_bfloat16 l1 = __float2bfloat16_rn(v.y - __bfloat162float(h1));
    __nv_bfloat16 l2 = __float2bfloat16_rn(v.z - __bfloat162float(h2));
    __nv_bfloat16 l3 = __float2bfloat16_rn(v.w - __bfloat162float(h3));
    oh.x = ((uint32_t)__bfloat16_as_ushort(h1) << 16) | __bfloat16_as_ushort(h0);
    oh.y = ((uint32_t)__bfloat16_as_ushort(h3) << 16) | __bfloat16_as_ushort(h2);
    ol.x = ((uint32_t)__bfloat16_as_ushort(l1) << 16) | __bfloat16_as_ushort(l0);
    ol.y = ((uint32_t)__bfloat16_as_ushort(l3) << 16) | __bfloat16_as_ushort(l2);
}
__device__ __forceinline__ void split_pair(float v0, float v1,
                                           uint32_t& h, uint32_t& lo) {
    __nv_bfloat16 h0 = __float2bfloat16_rn(v0);
    __nv_bfloat16 h1 = __float2bfloat16_rn(v1);
    __nv_bfloat16 l0 = __float2bfloat16_rn(v0 - __bfloat162float(h0));
    __nv_bfloat16 l1 = __float2bfloat16_rn(v1 - __bfloat162float(h1));
    h  = ((uint32_t)__bfloat16_as_ushort(h1) << 16) | __bfloat16_as_ushort(h0);
    lo = ((uint32_t)__bfloat16_as_ushort(l1) << 16) | __bfloat16_as_ushort(l0);
}

// ---------------------------------------------------------------------------
// Kernel A: convert x -> hi/lo bf16.
// ---------------------------------------------------------------------------
__global__ __launch_bounds__(256) void convert_x_kernel(const float* __restrict__ x)
{
    const int i = blockIdx.x * 256 + threadIdx.x;
    float4 v = reinterpret_cast<const float4*>(x)[i];
    uint2 oh, ol;
    split4(v, oh, ol);
    reinterpret_cast<uint2*>(x_hi)[i] = oh;
    reinterpret_cast<uint2*>(x_lo)[i] = ol;
}

// ---------------------------------------------------------------------------
// Kernel B: convert stacked W -> hi/lo bf16.
// ---------------------------------------------------------------------------
__global__ __launch_bounds__(256) void convert_w_kernel(
    const float* __restrict__ Wq, const float* __restrict__ Wk,
    const float* __restrict__ Wv)
{
    const int row = blockIdx.x;
    const float* src = (row < 64) ? (Wq + (size_t)row * EMB)
                     : (row < 128) ? (Wk + (size_t)(row - 64) * EMB)
                                   : (Wv + (size_t)(row - 128) * EMB);
    const int i = threadIdx.x;
    float4 v = reinterpret_cast<const float4*>(src)[i];
    uint2 oh, ol;
    split4(v, oh, ol);
    reinterpret_cast<uint2*>(w_hi)[(size_t)row * (EMB / 4) + i] = oh;
    reinterpret_cast<uint2*>(w_lo)[(size_t)row * (EMB / 4) + i] = ol;
}

// ---------------------------------------------------------------------------
// Kernel C: QKV GEMM via mma.sync bf16 (3-term split) — R8 mainloop.
// Epilogue now writes Q,K as bf16 hi/lo row-major; V fp32 row-major.
// ---------------------------------------------------------------------------
#define GPITCH 144
#define OFF_AH 0
#define OFF_AL 9216
#define OFF_BH 18432
#define OFF_BL 46080
#define GBUF   73728
#define GEMM_SMEM (2 * GBUF)
#define CHUNKS 16

__device__ __forceinline__ void qkv_stage_cp(uint32_t bufb, int c, int row0, int tid)
{
#pragma unroll
    for (int u = 0; u < 2; u++) {
        int idx = tid + u * 256;
        int r = idx >> 3, seg = idx & 7;
        uint32_t dst = r * GPITCH + seg * 16;
        cp16(bufb + OFF_AH + dst, &x_hi[(size_t)(row0 + r) * EMB + c * 64 + seg * 8]);
        cp16(bufb + OFF_AL + dst, &x_lo[(size_t)(row0 + r) * EMB + c * 64 + seg * 8]);
    }
#pragma unroll
    for (int u = 0; u < 6; u++) {
        int idx = tid + u * 256;
        int r = idx >> 3, seg = idx & 7;
        uint32_t dst = r * GPITCH + seg * 16;
        cp16(bufb + OFF_BH + dst, &w_hi[(size_t)r * EMB + c * 64 + seg * 8]);
        cp16(bufb + OFF_BL + dst, &w_lo[(size_t)r * EMB + c * 64 + seg * 8]);
    }
}

__global__ __launch_bounds__(256) void qkv_gemm_kernel()
{
    extern __shared__ char smg[];
    const uint32_t smb = smem_u32(smg);
    const int tid  = threadIdx.x;
    const int lane = tid & 31;
    const int w    = tid >> 5;
    const int wm   = w & 1;
    const int wn   = w >> 1;
    const int row0 = blockIdx.x * 64;

    float acc[2][6][4];
#pragma unroll
    for (int mm = 0; mm < 2; mm++)
#pragma unroll
        for (int nn = 0; nn < 6; nn++)
#pragma unroll
            for (int q = 0; q < 4; q++) acc[mm][nn][q] = 0.f;

    const int g01 = (lane >> 3) & 1;
    const int g23 = (lane >> 4);
    const int tr  = lane & 7;

    qkv_stage_cp(smb, 0, row0, tid);
    CP_COMMIT();

    for (int c = 0; c < CHUNKS; c++) {
        const uint32_t bufb = smb + (c & 1) * GBUF;
        if (c < CHUNKS - 1) {
            qkv_stage_cp(smb + ((c + 1) & 1) * GBUF, c + 1, row0, tid);
            CP_COMMIT();
            CP_WAIT(1);
        } else {
            CP_WAIT(0);
        }
        __syncthreads();

#pragma unroll
        for (int pass = 0; pass < 3; pass++) {
            const uint32_t aoff = (pass == 2) ? OFF_AL : OFF_AH;
            const uint32_t boff = (pass == 1) ? OFF_BL : OFF_BH;
#pragma unroll
            for (int ks = 0; ks < 4; ks++) {
                uint32_t afr[2][4];
#pragma unroll
                for (int mm = 0; mm < 2; mm++) {
                    uint32_t addr = bufb + aoff
                        + (uint32_t)(wm * 32 + mm * 16 + g01 * 8 + tr) * GPITCH
                        + (uint32_t)(ks * 16 + g23 * 8) * 2;
                    ldsm4(afr[mm], addr);
                }
                uint32_t bfr[3][4];
#pragma unroll
                for (int ng = 0; ng < 3; ng++) {
                    uint32_t addr = bufb + boff
                        + (uint32_t)(wn * 48 + ng * 16 + g23 * 8 + tr) * GPITCH
                        + (uint32_t)(ks * 16 + g01 * 8) * 2;
                    ldsm4(bfr[ng], addr);
                }
#pragma unroll
                for (int mm = 0; mm < 2; mm++)
#pragma unroll
                    for (int nn = 0; nn < 6; nn++)
                        mma_bf16(acc[mm][nn], afr[mm], &bfr[nn >> 1][(nn & 1) * 2]);
            }
        }
        __syncthreads();
    }

    const int mrow = lane >> 2;
    const int ncol = 2 * (lane & 3);
#pragma unroll
    for (int mm = 0; mm < 2; mm++) {
#pragma unroll
        for (int nn = 0; nn < 6; nn++) {
            const int n = wn * 48 + nn * 8 + ncol;
            const int m = row0 + wm * 32 + mm * 16 + mrow;
            const float* cvals = acc[mm][nn];
            if (n < 64) {
                uint32_t h01, l01, h23, l23;
                split_pair(cvals[0], cvals[1], h01, l01);
                split_pair(cvals[2], cvals[3], h23, l23);
                *reinterpret_cast<uint32_t*>(&q_hi[(size_t)m * HD + n]) = h01;
                *reinterpret_cast<uint32_t*>(&q_lo[(size_t)m * HD + n]) = l01;
                *reinterpret_cast<uint32_t*>(&q_hi[(size_t)(m + 8) * HD + n]) = h23;
                *reinterpret_cast<uint32_t*>(&q_lo[(size_t)(m + 8) * HD + n]) = l23;
            } else if (n < 128) {
                const int nk = n - 64;
                uint32_t h01, l01, h23, l23;
                split_pair(cvals[0], cvals[1], h01, l01);
                split_pair(cvals[2], cvals[3], h23, l23);
                *reinterpret_cast<uint32_t*>(&k_hi[(size_t)m * HD + nk]) = h01;
                *reinterpret_cast<uint32_t*>(&k_lo[(size_t)m * HD + nk]) = l01;
                *reinterpret_cast<uint32_t*>(&k_hi[(size_t)(m + 8) * HD + nk]) = h23;
                *reinterpret_cast<uint32_t*>(&k_lo[(size_t)(m + 8) * HD + nk]) = l23;
            } else {
                const int nv = n - 128;
                *reinterpret_cast<float2*>(&g_vs[(size_t)m * HD + nv]) =
                    make_float2(cvals[0], cvals[1]);
                *reinterpret_cast<float2*>(&g_vs[(size_t)(m + 8) * HD + nv]) =
                    make_float2(cvals[2], cvals[3]);
            }
        }
    }
}

// ---------------------------------------------------------------------------
// Kernel D: per-batch mean of V rows (parallel).
// ---------------------------------------------------------------------------
__global__ __launch_bounds__(256) void vmean1_kernel()
{
    const int b = blockIdx.x;
    const int c = blockIdx.y;
    const int d = threadIdx.x & 63;
    const int sub = threadIdx.x >> 6;
    float s = 0.f;
    const int i0 = c * 64 + sub * 16;
#pragma unroll 4
    for (int i = i0; i < i0 + 16; i++)
        s += g_vs[((size_t)b * SEQ + i) * HD + d];
    __shared__ float red[256];
    red[threadIdx.x] = s;
    __syncthreads();
    if (sub == 0)
        g_vpart[(b * 32 + c) * HD + d] =
            red[d] + red[64 + d] + red[128 + d] + red[192 + d];
}

__global__ __launch_bounds__(256) void vmean2_kernel()
{
    const int b = blockIdx.x;
    const int d = threadIdx.x & 63;
    const int sub = threadIdx.x >> 6;
    float s = 0.f;
#pragma unroll
    for (int c = sub * 8; c < sub * 8 + 8; c++)
        s += g_vpart[(b * 32 + c) * HD + d];
    __shared__ float red[256];
    red[threadIdx.x] = s;
    __syncthreads();
    if (sub == 0)
        g_vmean[b * HD + d] =
            (red[d] + red[64 + d] + red[128 + d] + red[192 + d]) * (1.0f / SEQ);
}

// ---------------------------------------------------------------------------
// Kernel E: attention partials — S = QK^T on tensor cores (bf16 3-pass
// mma.sync), softmax + PV(fma2) unchanged. 64-row q-tiles, 128-key tiles,
// 320 jobs. K single-buffer (restaged post-S), V double-buffered.
// smem bytes: QH 9216 | QL 9216 | KH 18432 | KL 18432 | V0 34816 | V1 34816
//             | S 33792 | PT 34816  = 193536 B
// ---------------------------------------------------------------------------
#define B_QH 0
#define B_QL 9216
#define B_KH 18432
#define B_KL 36864
#define B_V0 55296
#define B_V1 90112
#define B_S  124928
#define B_PT 158720
#define ATTN_SMEM 193536
#define PS  132      // S pitch (fp32 words)
#define PV2 68       // V pitch (fp32 words)
#define PP2 68       // P pitch (fp32 words)

__global__ __launch_bounds__(256) void attn_partial_kernel(
    const int* __restrict__ pad)
{
    const int bid = blockIdx.x;
    const int b = bid / 80;
    const int rem = bid - b * 80;
    int jq, ch;
    if (rem < 8)       { jq = rem;                   ch = 0; }
    else if (rem < 24) { jq = 8 + ((rem - 8) >> 1);  ch = (rem - 8) & 1; }
    else if (rem < 48) { jq = 16 + (rem - 24) / 3;   ch = (rem - 24) % 3; }
    else               { jq = 24 + ((rem - 48) >> 2); ch = (rem - 48) & 3; }
    const int q0 = jq * 64;
    const int kstart = ch * 512;
    const int kmax = q0 + 64;
    const int kend = (kstart + 512 < kmax) ? kstart + 512 : kmax;
    const int nkt = (kend - kstart + 127) >> 7;

    const int tid  = threadIdx.x;
    const int lane = tid & 31;
    const int wid  = tid >> 5;
    const int ty8  = wid * 8;

    extern __shared__ float smem[];
    const uint32_t smb = smem_u32(smem);
    float* sS  = smem + B_S / 4;
    float* sPt = smem + B_PT / 4;
    __shared__ int sPad[2][128];

    // ldmatrix lane address components
    const int g01 = (lane >> 3) & 1;
    const int g23 = (lane >> 4);
    const int tr  = lane & 7;
    // S-mma warp assignment: rows (wid&3)*16, keys (wid>>2)*64
    const int sw_r0 = (wid & 3) * 16;
    const int sw_kb = (wid >> 2) * 64;

    // prologue staging: Q (hi/lo), K(kstart), V->buf0, pad->sPad[0]
#pragma unroll
    for (int u = 0; u < 2; u++) {
        int idx = tid + u * 256;           // 0..511
        int r = idx >> 3, seg = idx & 7;
        cp16(smb + B_QH + r * 144 + seg * 16,
             &q_hi[(size_t)(b * SEQ + q0 + r) * HD + seg * 8]);
        cp16(smb + B_QL + r * 144 + seg * 16,
             &q_lo[(size_t)(b * SEQ + q0 + r) * HD + seg * 8]);
    }
#pragma unroll
    for (int u = 0; u < 4; u++) {
        int idx = tid + u * 256;           // 0..1023
        int key = idx >> 3, seg = idx & 7;
        cp16(smb + B_KH + key * 144 + seg * 16,
             &k_hi[(size_t)(b * SEQ + kstart + key) * HD + seg * 8]);
        cp16(smb + B_KL + key * 144 + seg * 16,
             &k_lo[(size_t)(b * SEQ + kstart + key) * HD + seg * 8]);
    }
#pragma unroll
    for (int u = 0; u < 8; u++) {
        int idx = tid + u * 256;
        int r = idx >> 4, f = (idx & 15) * 4;
        cp16(smb + B_V0 + (uint32_t)(r * PV2 + f) * 4,
             &g_vs[((size_t)b * SEQ + kstart + r) * HD + f]);
    }
    if (tid < 128) sPad[0][tid] = pad[b * SEQ + kstart + tid];
    CP_COMMIT();

    float m[8], l[8];
    u64 o2[4][2];
#pragma unroll
    for (int r = 0; r < 8; r++) { m[r] = -3.0e38f; l[r] = 0.f; }
#pragma unroll
    for (int p = 0; p < 4; p++) { o2[p][0] = 0ULL; o2[p][1] = 0ULL; }

    for (int kt = 0; kt < nkt; kt++) {
        const int cb = kt & 1;
        const int k0 = kstart + kt * 128;
        CP_WAIT(0);
        __syncthreads();               // K(kt), V(kt), pad(kt) visible; sS free

        // ---- S = Q K^T via mma.sync, 3-pass bf16 split ----
        float sacc[8][4];
#pragma unroll
        for (int nn = 0; nn < 8; nn++)
#pragma unroll
            for (int q = 0; q < 4; q++) sacc[nn][q] = 0.f;
#pragma unroll
        for (int pass = 0; pass < 3; pass++) {
            const uint32_t qoff = (pass == 2) ? B_QL : B_QH;
            const uint32_t koff = (pass == 1) ? B_KL : B_KH;
#pragma unroll
            for (int ks = 0; ks < 4; ks++) {
                uint32_t afr[4];
                ldsm4(afr, smb + qoff
                      + (uint32_t)(sw_r0 + g01 * 8 + tr) * 144
                      + (uint32_t)(ks * 16 + g23 * 8) * 2);
#pragma unroll
                for (int ng = 0; ng < 4; ng++) {
                    uint32_t bfr[4];
                    ldsm4(bfr, smb + koff
                          + (uint32_t)(sw_kb + ng * 16 + g23 * 8 + tr) * 144
                          + (uint32_t)(ks * 16 + g01 * 8) * 2);
                    mma_bf16(sacc[ng * 2 + 0], afr, bfr);
                    mma_bf16(sacc[ng * 2 + 1], afr, bfr + 2);
                }
            }
        }
        // store S fragments to smem (C-layout -> [row][key])
        {
            const int a = lane >> 2, q2 = 2 * (lane & 3);
#pragma unroll
            for (int nn = 0; nn < 8; nn++) {
                const int c = sw_kb + nn * 8 + q2;
                *reinterpret_cast<float2*>(&sS[(sw_r0 + a) * PS + c]) =
                    make_float2(sacc[nn][0], sacc[nn][1]);
                *reinterpret_cast<float2*>(&sS[(sw_r0 + a + 8) * PS + c]) =
                    make_float2(sacc[nn][2], sacc[nn][3]);
            }
        }
        __syncthreads();               // S visible; K dead

        // prefetch next tile: K restage (single buf) + V into cb^1 + pad
        if (kt + 1 < nkt) {
            const int k1 = k0 + 128;
#pragma unroll
            for (int u = 0; u < 4; u++) {
                int idx = tid + u * 256;
                int key = idx >> 3, seg = idx & 7;
                cp16(smb + B_KH + key * 144 + seg * 16,
                     &k_hi[(size_t)(b * SEQ + k1 + key) * HD + seg * 8]);
                cp16(smb + B_KL + key * 144 + seg * 16,
                     &k_lo[(size_t)(b * SEQ + k1 + key) * HD + seg * 8]);
            }
            const uint32_t vb = (cb == 0) ? (smb + B_V1) : (smb + B_V0);
#pragma unroll
            for (int u = 0; u < 8; u++) {
                int idx = tid + u * 256;
                int r = idx >> 4, f = (idx & 15) * 4;
                cp16(vb + (uint32_t)(r * PV2 + f) * 4,
                     &g_vs[((size_t)b * SEQ + k1 + r) * HD + f]);
            }
            if (tid < 128) sPad[cb ^ 1][tid] = pad[b * SEQ + k1 + tid];
            CP_COMMIT();
        }

        // ---- mask + online softmax (reads sS rows ty8..ty8+7) ----
        const int* sPadC = sPad[cb];
        float p8[8][4], scl[8];
#pragma unroll
        for (int r = 0; r < 8; r++) {
            const int qi = q0 + ty8 + r;
            float4 sv4 = *reinterpret_cast<const float4*>(
                &sS[(ty8 + r) * PS + lane * 4]);
            float sv[4] = {sv4.x, sv4.y, sv4.z, sv4.w};
#pragma unroll
            for (int i = 0; i < 4; i++) {
                const int kj = k0 + lane * 4 + i;
                const bool masked = (kj > qi) || (sPadC[lane * 4 + i] == 0);
                sv[i] = (masked ? -1e9f : sv[i]) * 0.125f;
            }
            float tm = fmaxf(fmaxf(sv[0], sv[1]), fmaxf(sv[2], sv[3]));
            tm = fmaxf(tm, __shfl_xor_sync(0xffffffffu, tm, 1));
            tm = fmaxf(tm, __shfl_xor_sync(0xffffffffu, tm, 2));
            tm = fmaxf(tm, __shfl_xor_sync(0xffffffffu, tm, 4));
            tm = fmaxf(tm, __shfl_xor_sync(0xffffffffu, tm, 8));
            tm = fmaxf(tm, __shfl_xor_sync(0xffffffffu, tm, 16));
            const float mnew = fmaxf(m[r], tm);
            scl[r] = __expf(m[r] - mnew);
            float tl = 0.f;
#pragma unroll
            for (int i = 0; i < 4; i++) { p8[r][i] = __expf(sv[i] - mnew); tl += p8[r][i]; }
            tl += __shfl_xor_sync(0xffffffffu, tl, 1);
            tl += __shfl_xor_sync(0xffffffffu, tl, 2);
            tl += __shfl_xor_sync(0xffffffffu, tl, 4);
            tl += __shfl_xor_sync(0xffffffffu, tl, 8);
            tl += __shfl_xor_sync(0xffffffffu, tl, 16);
            l[r] = l[r] * scl[r] + tl;
            m[r] = mnew;
        }
#pragma unroll
        for (int p = 0; p < 4; p++) {
            u64 sp = pack2(scl[2 * p], scl[2 * p + 1]);
            mul2(o2[p][0], sp);
            mul2(o2[p][1], sp);
        }
#pragma unroll
        for (int i = 0; i < 4; i++) {
            const int key = lane * 4 + i;
            *reinterpret_cast<float4*>(&sPt[key * PP2 + ty8]) =
                make_float4(p8[0][i], p8[1][i], p8[2][i], p8[3][i]);
            *reinterpret_cast<float4*>(&sPt[key * PP2 + ty8 + 4]) =
                make_float4(p8[4][i], p8[5][i], p8[6][i], p8[7][i]);
        }
        __syncthreads();               // P visible

        // ---- O += P V (fma2) ----
        const float* sV = smem + (cb == 0 ? B_V0 : B_V1) / 4;
#pragma unroll 8
        for (int j = 0; j < 128; j++) {
            ulonglong2 pA = *reinterpret_cast<const ulonglong2*>(&sPt[j * PP2 + ty8]);
            ulonglong2 pB = *reinterpret_cast<const ulonglong2*>(&sPt[j * PP2 + ty8 + 4]);
            float2 v2 = *reinterpret_cast<const float2*>(&sV[j * PV2 + lane * 2]);
            u64 v0 = splat2(v2.x), v1 = splat2(v2.y);
            fma2(o2[0][0], pA.x, v0); fma2(o2[0][1], pA.x, v1);
            fma2(o2[1][0], pA.y, v0); fma2(o2[1][1], pA.y, v1);
            fma2(o2[2][0], pB.x, v0); fma2(o2[2][1], pB.x, v1);
            fma2(o2[3][0], pB.y, v0); fma2(o2[3][1], pB.y, v1);
        }
    }

    if (lane == 0) {
#pragma unroll
        for (int r = 0; r < 8; r++) {
            g_pm[bid * 64 + ty8 + r] = m[r];
            g_pl[bid * 64 + ty8 + r] = l[r];
        }
    }
#pragma unroll
    for (int p = 0; p < 4; p++) {
        float aLo, aHi, bLo, bHi;
        unpack2(o2[p][0], aLo, aHi);
        unpack2(o2[p][1], bLo, bHi);
        *reinterpret_cast<float2*>(
            &g_po[(size_t)bid * 4096 + (ty8 + 2 * p) * 64 + lane * 2]) =
            make_float2(aLo, bLo);
        *reinterpret_cast<float2*>(
            &g_po[(size_t)bid * 4096 + (ty8 + 2 * p + 1) * 64 + lane * 2]) =
            make_float2(aHi, bHi);
    }
}

// ---------------------------------------------------------------------------
// Kernel F: merge partials.
// ---------------------------------------------------------------------------
__global__ __launch_bounds__(256) void attn_merge_kernel(float* __restrict__ out)
{
    const int b  = blockIdx.x >> 5;
    const int jq = blockIdx.x & 31;
    int off;
    if (jq < 8)       off = jq;
    else if (jq < 16) off = 8 + 2 * (jq - 8);
    else if (jq < 24) off = 24 + 3 * (jq - 16);
    else              off = 48 + 4 * (jq - 24);
    const int nch = (jq >> 3) + 1;
    const int jbase = b * 80 + off;
    const int q0 = jq * 64;

    const int d  = threadIdx.x & 63;
    const int r0 = threadIdx.x >> 6;

    for (int rr = 0; rr < 16; rr++) {
        const int row = r0 + rr * 4;
        float M = -3.0e38f;
        float mi[5], li[5];
#pragma unroll 5
        for (int i = 0; i < 5; i++) {
            if (i < nch) {
                mi[i] = g_pm[(jbase + i) * 64 + row];
                li[i] = g_pl[(jbase + i) * 64 + row];
                M = fmaxf(M, mi[i]);
            }
        }
        float L = 0.f, O = 0.f;
#pragma unroll 5
        for (int i = 0; i < 5; i++) {
            if (i < nch) {
                float w = __expf(mi[i] - M);
                L += li[i] * w;
                O += g_po[(size_t)(jbase + i) * 4096 + row * 64 + d] * w;
            }
        }
        float res = (M <= -1.0e8f) ? g_vmean[b * HD + d] : O / L;
        out[((size_t)b * SEQ + q0 + row) * HD + d] = res;
    }
}

// ---------------------------------------------------------------------------
extern "C" void kernel_launch(void* const* d_in, const int* in_sizes, int n_in,
                              void* d_out, int out_size)
{
    const float* x   = (const float*)d_in[0];
    const int*   pad = (const int*)  d_in[1];
    const float* Wq  = (const float*)d_in[2];
    const float* Wk  = (const float*)d_in[3];
    const float* Wv  = (const float*)d_in[4];
    float* out = (float*)d_out;

    cudaFuncSetAttribute(qkv_gemm_kernel,
                         cudaFuncAttributeMaxDynamicSharedMemorySize, GEMM_SMEM);
    cudaFuncSetAttribute(attn_partial_kernel,
                         cudaFuncAttributeMaxDynamicSharedMemorySize, ATTN_SMEM);

    convert_x_kernel<<<(MTOT * EMB / 4) / 256, 256>>>(x);
    convert_w_kernel<<<192, 256>>>(Wq, Wk, Wv);
    qkv_gemm_kernel<<<128, 256, GEMM_SMEM>>>();
    vmean1_kernel<<<dim3(BSZ, 32), 256>>>();
    vmean2_kernel<<<BSZ, 256>>>();
    attn_partial_kernel<<<NJOBS, 256, ATTN_SMEM>>>(pad);
    attn_merge_kernel<<<128, 256>>>(out);
}

// round 17
// speedup vs baseline: 1.6992x; 1.0490x over previous
#include <cuda_runtime.h>
#include <cuda_bf16.h>
#include <cstdint>

#define BSZ 4
#define SEQ 2048
#define EMB 1024
#define HD  64
#define MTOT (BSZ * SEQ)

// bf16 split operands
__device__ __nv_bfloat16 x_hi[MTOT * EMB];
__device__ __nv_bfloat16 x_lo[MTOT * EMB];
__device__ __nv_bfloat16 w_hi[192 * EMB];
__device__ __nv_bfloat16 w_lo[192 * EMB];
// projection outputs: Q,K bf16 hi/lo row-major [row][64]; V fp32 row-major
__device__ __nv_bfloat16 q_hi[MTOT * HD];
__device__ __nv_bfloat16 q_lo[MTOT * HD];
__device__ __nv_bfloat16 k_hi[MTOT * HD];
__device__ __nv_bfloat16 k_lo[MTOT * HD];
__device__ float g_vs[MTOT * HD];
// vmean partials (final reduce folded into merge kernel)
__device__ float g_vpart[BSZ * 32 * HD];
// attention split-key partials: 320 jobs (80 per batch, 512-key chunks)
#define NJOBS 320
__device__ float g_pm[NJOBS * 64];
__device__ float g_pl[NJOBS * 64];
__device__ float g_po[NJOBS * 64 * 64];

typedef unsigned long long u64;

__device__ __forceinline__ u64 splat2(float x) {
    u64 r; asm("mov.b64 %0, {%1, %1};" : "=l"(r) : "f"(x)); return r;
}
__device__ __forceinline__ u64 pack2(float lo, float hi) {
    u64 r; asm("mov.b64 %0, {%1, %2};" : "=l"(r) : "f"(lo), "f"(hi)); return r;
}
__device__ __forceinline__ void fma2(u64& d, u64 a, u64 b) {
    asm("fma.rn.f32x2 %0, %1, %2, %0;" : "+l"(d) : "l"(a), "l"(b));
}
__device__ __forceinline__ void mul2(u64& d, u64 s) {
    asm("mul.rn.f32x2 %0, %0, %1;" : "+l"(d) : "l"(s));
}
__device__ __forceinline__ void unpack2(u64 v, float& lo, float& hi) {
    asm("mov.b64 {%0, %1}, %2;" : "=f"(lo), "=f"(hi) : "l"(v));
}
__device__ __forceinline__ uint32_t smem_u32(const void* p) {
    uint32_t a;
    asm("{ .reg .u64 t; cvta.to.shared.u64 t, %1; cvt.u32.u64 %0, t; }"
        : "=r"(a) : "l"(p));
    return a;
}

// ---- portable tensor-core helpers ----------------------------------------
__device__ __forceinline__ void mma_bf16(float* d, const uint32_t* a,
                                         const uint32_t* b) {
    asm volatile(
        "mma.sync.aligned.m16n8k16.row.col.f32.bf16.bf16.f32 "
        "{%0,%1,%2,%3}, {%4,%5,%6,%7}, {%8,%9}, {%0,%1,%2,%3};"
        : "+f"(d[0]), "+f"(d[1]), "+f"(d[2]), "+f"(d[3])
        : "r"(a[0]), "r"(a[1]), "r"(a[2]), "r"(a[3]), "r"(b[0]), "r"(b[1]));
}
__device__ __forceinline__ void ldsm4(uint32_t* r, uint32_t addr) {
    asm volatile("ldmatrix.sync.aligned.m8n8.x4.shared.b16 {%0,%1,%2,%3}, [%4];"
                 : "=r"(r[0]), "=r"(r[1]), "=r"(r[2]), "=r"(r[3]) : "r"(addr));
}
__device__ __forceinline__ void cp16(uint32_t smaddr, const void* g) {
    asm volatile("cp.async.ca.shared.global [%0], [%1], 16;"
                 :: "r"(smaddr), "l"(g));
}
#define CP_COMMIT()  asm volatile("cp.async.commit_group;" ::: "memory")
#define CP_WAIT(n)   asm volatile("cp.async.wait_group %0;" :: "n"(n) : "memory")

// ---- bf16 hi/lo split helpers ---------------------------------------------
__device__ __forceinline__ void split4(float4 v, uint2& oh, uint2& ol) {
    __nv_bfloat16 h0 = __float2bfloat16_rn(v.x);
    __nv_bfloat16 h1 = __float2bfloat16_rn(v.y);
    __nv_bfloat16 h2 = __float2bfloat16_rn(v.z);
    __nv_bfloat16 h3 = __float2bfloat16_rn(v.w);
    __nv_bfloat16 l0 = __float2bfloat16_rn(v.x - __bfloat162float(h0));
    __nv_bfloat16 l1 = __float2bfloat16_rn(v.y - __bfloat162float(h1));
    __nv_bfloat16 l2 = __float2bfloat16_rn(v.z - __bfloat162float(h2));
    __nv_bfloat16 l3 = __float2bfloat16_rn(v.w - __bfloat162float(h3));
    oh.x = ((uint32_t)__bfloat16_as_ushort(h1) << 16) | __bfloat16_as_ushort(h0);
    oh.y = ((uint32_t)__bfloat16_as_ushort(h3) << 16) | __bfloat16_as_ushort(h2);
    ol.x = ((uint32_t)__bfloat16_as_ushort(l1) << 16) | __bfloat16_as_ushort(l0);
    ol.y = ((uint32_t)__bfloat16_as_ushort(l3) << 16) | __bfloat16_as_ushort(l2);
}
__device__ __forceinline__ void split_pair(float v0, float v1,
                                           uint32_t& h, uint32_t& lo) {
    __nv_bfloat16 h0 = __float2bfloat16_rn(v0);
    __nv_bfloat16 h1 = __float2bfloat16_rn(v1);
    __nv_bfloat16 l0 = __float2bfloat16_rn(v0 - __bfloat162float(h0));
    __nv_bfloat16 l1 = __float2bfloat16_rn(v1 - __bfloat162float(h1));
    h  = ((uint32_t)__bfloat16_as_ushort(h1) << 16) | __bfloat16_as_ushort(h0);
    lo = ((uint32_t)__bfloat16_as_ushort(l1) << 16) | __bfloat16_as_ushort(l0);
}

// ---------------------------------------------------------------------------
// Kernel A: fused convert — blocks <8192 convert x, blocks >=8192 convert W.
// ---------------------------------------------------------------------------
__global__ __launch_bounds__(256) void convert_all_kernel(
    const float* __restrict__ x,
    const float* __restrict__ Wq, const float* __restrict__ Wk,
    const float* __restrict__ Wv)
{
    if (blockIdx.x < 8192) {
        const int i = blockIdx.x * 256 + threadIdx.x;
        float4 v = reinterpret_cast<const float4*>(x)[i];
        uint2 oh, ol;
        split4(v, oh, ol);
        reinterpret_cast<uint2*>(x_hi)[i] = oh;
        reinterpret_cast<uint2*>(x_lo)[i] = ol;
    } else {
        const int row = blockIdx.x - 8192;
        const float* src = (row < 64) ? (Wq + (size_t)row * EMB)
                         : (row < 128) ? (Wk + (size_t)(row - 64) * EMB)
                                       : (Wv + (size_t)(row - 128) * EMB);
        const int i = threadIdx.x;
        float4 v = reinterpret_cast<const float4*>(src)[i];
        uint2 oh, ol;
        split4(v, oh, ol);
        reinterpret_cast<uint2*>(w_hi)[(size_t)row * (EMB / 4) + i] = oh;
        reinterpret_cast<uint2*>(w_lo)[(size_t)row * (EMB / 4) + i] = ol;
    }
}

// ---------------------------------------------------------------------------
// Kernel C: QKV GEMM via mma.sync bf16 (3-term split) — unchanged from R15.
// ---------------------------------------------------------------------------
#define GPITCH 144
#define OFF_AH 0
#define OFF_AL 9216
#define OFF_BH 18432
#define OFF_BL 46080
#define GBUF   73728
#define GEMM_SMEM (2 * GBUF)
#define CHUNKS 16

__device__ __forceinline__ void qkv_stage_cp(uint32_t bufb, int c, int row0, int tid)
{
#pragma unroll
    for (int u = 0; u < 2; u++) {
        int idx = tid + u * 256;
        int r = idx >> 3, seg = idx & 7;
        uint32_t dst = r * GPITCH + seg * 16;
        cp16(bufb + OFF_AH + dst, &x_hi[(size_t)(row0 + r) * EMB + c * 64 + seg * 8]);
        cp16(bufb + OFF_AL + dst, &x_lo[(size_t)(row0 + r) * EMB + c * 64 + seg * 8]);
    }
#pragma unroll
    for (int u = 0; u < 6; u++) {
        int idx = tid + u * 256;
        int r = idx >> 3, seg = idx & 7;
        uint32_t dst = r * GPITCH + seg * 16;
        cp16(bufb + OFF_BH + dst, &w_hi[(size_t)r * EMB + c * 64 + seg * 8]);
        cp16(bufb + OFF_BL + dst, &w_lo[(size_t)r * EMB + c * 64 + seg * 8]);
    }
}

__global__ __launch_bounds__(256) void qkv_gemm_kernel()
{
    extern __shared__ char smg[];
    const uint32_t smb = smem_u32(smg);
    const int tid  = threadIdx.x;
    const int lane = tid & 31;
    const int w    = tid >> 5;
    const int wm   = w & 1;
    const int wn   = w >> 1;
    const int row0 = blockIdx.x * 64;

    float acc[2][6][4];
#pragma unroll
    for (int mm = 0; mm < 2; mm++)
#pragma unroll
        for (int nn = 0; nn < 6; nn++)
#pragma unroll
            for (int q = 0; q < 4; q++) acc[mm][nn][q] = 0.f;

    const int g01 = (lane >> 3) & 1;
    const int g23 = (lane >> 4);
    const int tr  = lane & 7;

    qkv_stage_cp(smb, 0, row0, tid);
    CP_COMMIT();

    for (int c = 0; c < CHUNKS; c++) {
        const uint32_t bufb = smb + (c & 1) * GBUF;
        if (c < CHUNKS - 1) {
            qkv_stage_cp(smb + ((c + 1) & 1) * GBUF, c + 1, row0, tid);
            CP_COMMIT();
            CP_WAIT(1);
        } else {
            CP_WAIT(0);
        }
        __syncthreads();

#pragma unroll
        for (int pass = 0; pass < 3; pass++) {
            const uint32_t aoff = (pass == 2) ? OFF_AL : OFF_AH;
            const uint32_t boff = (pass == 1) ? OFF_BL : OFF_BH;
#pragma unroll
            for (int ks = 0; ks < 4; ks++) {
                uint32_t afr[2][4];
#pragma unroll
                for (int mm = 0; mm < 2; mm++) {
                    uint32_t addr = bufb + aoff
                        + (uint32_t)(wm * 32 + mm * 16 + g01 * 8 + tr) * GPITCH
                        + (uint32_t)(ks * 16 + g23 * 8) * 2;
                    ldsm4(afr[mm], addr);
                }
                uint32_t bfr[3][4];
#pragma unroll
                for (int ng = 0; ng < 3; ng++) {
                    uint32_t addr = bufb + boff
                        + (uint32_t)(wn * 48 + ng * 16 + g23 * 8 + tr) * GPITCH
                        + (uint32_t)(ks * 16 + g01 * 8) * 2;
                    ldsm4(bfr[ng], addr);
                }
#pragma unroll
                for (int mm = 0; mm < 2; mm++)
#pragma unroll
                    for (int nn = 0; nn < 6; nn++)
                        mma_bf16(acc[mm][nn], afr[mm], &bfr[nn >> 1][(nn & 1) * 2]);
            }
        }
        __syncthreads();
    }

    const int mrow = lane >> 2;
    const int ncol = 2 * (lane & 3);
#pragma unroll
    for (int mm = 0; mm < 2; mm++) {
#pragma unroll
        for (int nn = 0; nn < 6; nn++) {
            const int n = wn * 48 + nn * 8 + ncol;
            const int m = row0 + wm * 32 + mm * 16 + mrow;
            const float* cvals = acc[mm][nn];
            if (n < 64) {
                uint32_t h01, l01, h23, l23;
                split_pair(cvals[0], cvals[1], h01, l01);
                split_pair(cvals[2], cvals[3], h23, l23);
                *reinterpret_cast<uint32_t*>(&q_hi[(size_t)m * HD + n]) = h01;
                *reinterpret_cast<uint32_t*>(&q_lo[(size_t)m * HD + n]) = l01;
                *reinterpret_cast<uint32_t*>(&q_hi[(size_t)(m + 8) * HD + n]) = h23;
                *reinterpret_cast<uint32_t*>(&q_lo[(size_t)(m + 8) * HD + n]) = l23;
            } else if (n < 128) {
                const int nk = n - 64;
                uint32_t h01, l01, h23, l23;
                split_pair(cvals[0], cvals[1], h01, l01);
                split_pair(cvals[2], cvals[3], h23, l23);
                *reinterpret_cast<uint32_t*>(&k_hi[(size_t)m * HD + nk]) = h01;
                *reinterpret_cast<uint32_t*>(&k_lo[(size_t)m * HD + nk]) = l01;
                *reinterpret_cast<uint32_t*>(&k_hi[(size_t)(m + 8) * HD + nk]) = h23;
                *reinterpret_cast<uint32_t*>(&k_lo[(size_t)(m + 8) * HD + nk]) = l23;
            } else {
                const int nv = n - 128;
                *reinterpret_cast<float2*>(&g_vs[(size_t)m * HD + nv]) =
                    make_float2(cvals[0], cvals[1]);
                *reinterpret_cast<float2*>(&g_vs[(size_t)(m + 8) * HD + nv]) =
                    make_float2(cvals[2], cvals[3]);
            }
        }
    }
}

// ---------------------------------------------------------------------------
// Kernel D: per-batch V-row partial sums (final reduce happens in merge).
// ---------------------------------------------------------------------------
__global__ __launch_bounds__(256) void vmean1_kernel()
{
    const int b = blockIdx.x;
    const int c = blockIdx.y;
    const int d = threadIdx.x & 63;
    const int sub = threadIdx.x >> 6;
    float s = 0.f;
    const int i0 = c * 64 + sub * 16;
#pragma unroll 4
    for (int i = i0; i < i0 + 16; i++)
        s += g_vs[((size_t)b * SEQ + i) * HD + d];
    __shared__ float red[256];
    red[threadIdx.x] = s;
    __syncthreads();
    if (sub == 0)
        g_vpart[(b * 32 + c) * HD + d] =
            red[d] + red[64 + d] + red[128 + d] + red[192 + d];
}

// ---------------------------------------------------------------------------
// Kernel E: attention partials — byte-identical to R15.
// ---------------------------------------------------------------------------
#define B_QH 0
#define B_QL 9216
#define B_KH 18432
#define B_KL 36864
#define B_V0 55296
#define B_V1 90112
#define B_S  124928
#define B_PT 158720
#define ATTN_SMEM 193536
#define PS  132
#define PV2 68
#define PP2 68

__global__ __launch_bounds__(256) void attn_partial_kernel(
    const int* __restrict__ pad)
{
    const int bid = blockIdx.x;
    const int b = bid / 80;
    const int rem = bid - b * 80;
    int jq, ch;
    if (rem < 8)       { jq = rem;                   ch = 0; }
    else if (rem < 24) { jq = 8 + ((rem - 8) >> 1);  ch = (rem - 8) & 1; }
    else if (rem < 48) { jq = 16 + (rem - 24) / 3;   ch = (rem - 24) % 3; }
    else               { jq = 24 + ((rem - 48) >> 2); ch = (rem - 48) & 3; }
    const int q0 = jq * 64;
    const int kstart = ch * 512;
    const int kmax = q0 + 64;
    const int kend = (kstart + 512 < kmax) ? kstart + 512 : kmax;
    const int nkt = (kend - kstart + 127) >> 7;

    const int tid  = threadIdx.x;
    const int lane = tid & 31;
    const int wid  = tid >> 5;
    const int ty8  = wid * 8;

    extern __shared__ float smem[];
    const uint32_t smb = smem_u32(smem);
    float* sS  = smem + B_S / 4;
    float* sPt = smem + B_PT / 4;
    __shared__ int sPad[2][128];

    const int g01 = (lane >> 3) & 1;
    const int g23 = (lane >> 4);
    const int tr  = lane & 7;
    const int sw_r0 = (wid & 3) * 16;
    const int sw_kb = (wid >> 2) * 64;

#pragma unroll
    for (int u = 0; u < 2; u++) {
        int idx = tid + u * 256;
        int r = idx >> 3, seg = idx & 7;
        cp16(smb + B_QH + r * 144 + seg * 16,
             &q_hi[(size_t)(b * SEQ + q0 + r) * HD + seg * 8]);
        cp16(smb + B_QL + r * 144 + seg * 16,
             &q_lo[(size_t)(b * SEQ + q0 + r) * HD + seg * 8]);
    }
#pragma unroll
    for (int u = 0; u < 4; u++) {
        int idx = tid + u * 256;
        int key = idx >> 3, seg = idx & 7;
        cp16(smb + B_KH + key * 144 + seg * 16,
             &k_hi[(size_t)(b * SEQ + kstart + key) * HD + seg * 8]);
        cp16(smb + B_KL + key * 144 + seg * 16,
             &k_lo[(size_t)(b * SEQ + kstart + key) * HD + seg * 8]);
    }
#pragma unroll
    for (int u = 0; u < 8; u++) {
        int idx = tid + u * 256;
        int r = idx >> 4, f = (idx & 15) * 4;
        cp16(smb + B_V0 + (uint32_t)(r * PV2 + f) * 4,
             &g_vs[((size_t)b * SEQ + kstart + r) * HD + f]);
    }
    if (tid < 128) sPad[0][tid] = pad[b * SEQ + kstart + tid];
    CP_COMMIT();

    float m[8], l[8];
    u64 o2[4][2];
#pragma unroll
    for (int r = 0; r < 8; r++) { m[r] = -3.0e38f; l[r] = 0.f; }
#pragma unroll
    for (int p = 0; p < 4; p++) { o2[p][0] = 0ULL; o2[p][1] = 0ULL; }

    for (int kt = 0; kt < nkt; kt++) {
        const int cb = kt & 1;
        const int k0 = kstart + kt * 128;
        CP_WAIT(0);
        __syncthreads();

        float sacc[8][4];
#pragma unroll
        for (int nn = 0; nn < 8; nn++)
#pragma unroll
            for (int q = 0; q < 4; q++) sacc[nn][q] = 0.f;
#pragma unroll
        for (int pass = 0; pass < 3; pass++) {
            const uint32_t qoff = (pass == 2) ? B_QL : B_QH;
            const uint32_t koff = (pass == 1) ? B_KL : B_KH;
#pragma unroll
            for (int ks = 0; ks < 4; ks++) {
                uint32_t afr[4];
                ldsm4(afr, smb + qoff
                      + (uint32_t)(sw_r0 + g01 * 8 + tr) * 144
                      + (uint32_t)(ks * 16 + g23 * 8) * 2);
#pragma unroll
                for (int ng = 0; ng < 4; ng++) {
                    uint32_t bfr[4];
                    ldsm4(bfr, smb + koff
                          + (uint32_t)(sw_kb + ng * 16 + g23 * 8 + tr) * 144
                          + (uint32_t)(ks * 16 + g01 * 8) * 2);
                    mma_bf16(sacc[ng * 2 + 0], afr, bfr);
                    mma_bf16(sacc[ng * 2 + 1], afr, bfr + 2);
                }
            }
        }
        {
            const int a = lane >> 2, q2 = 2 * (lane & 3);
#pragma unroll
            for (int nn = 0; nn < 8; nn++) {
                const int c = sw_kb + nn * 8 + q2;
                *reinterpret_cast<float2*>(&sS[(sw_r0 + a) * PS + c]) =
                    make_float2(sacc[nn][0], sacc[nn][1]);
                *reinterpret_cast<float2*>(&sS[(sw_r0 + a + 8) * PS + c]) =
                    make_float2(sacc[nn][2], sacc[nn][3]);
            }
        }
        __syncthreads();

        if (kt + 1 < nkt) {
            const int k1 = k0 + 128;
#pragma unroll
            for (int u = 0; u < 4; u++) {
                int idx = tid + u * 256;
                int key = idx >> 3, seg = idx & 7;
                cp16(smb + B_KH + key * 144 + seg * 16,
                     &k_hi[(size_t)(b * SEQ + k1 + key) * HD + seg * 8]);
                cp16(smb + B_KL + key * 144 + seg * 16,
                     &k_lo[(size_t)(b * SEQ + k1 + key) * HD + seg * 8]);
            }
            const uint32_t vb = (cb == 0) ? (smb + B_V1) : (smb + B_V0);
#pragma unroll
            for (int u = 0; u < 8; u++) {
                int idx = tid + u * 256;
                int r = idx >> 4, f = (idx & 15) * 4;
                cp16(vb + (uint32_t)(r * PV2 + f) * 4,
                     &g_vs[((size_t)b * SEQ + k1 + r) * HD + f]);
            }
            if (tid < 128) sPad[cb ^ 1][tid] = pad[b * SEQ + k1 + tid];
            CP_COMMIT();
        }

        const int* sPadC = sPad[cb];
        float p8[8][4], scl[8];
#pragma unroll
        for (int r = 0; r < 8; r++) {
            const int qi = q0 + ty8 + r;
            float4 sv4 = *reinterpret_cast<const float4*>(
                &sS[(ty8 + r) * PS + lane * 4]);
            float sv[4] = {sv4.x, sv4.y, sv4.z, sv4.w};
#pragma unroll
            for (int i = 0; i < 4; i++) {
                const int kj = k0 + lane * 4 + i;
                const bool masked = (kj > qi) || (sPadC[lane * 4 + i] == 0);
                sv[i] = (masked ? -1e9f : sv[i]) * 0.125f;
            }
            float tm = fmaxf(fmaxf(sv[0], sv[1]), fmaxf(sv[2], sv[3]));
            tm = fmaxf(tm, __shfl_xor_sync(0xffffffffu, tm, 1));
            tm = fmaxf(tm, __shfl_xor_sync(0xffffffffu, tm, 2));
            tm = fmaxf(tm, __shfl_xor_sync(0xffffffffu, tm, 4));
            tm = fmaxf(tm, __shfl_xor_sync(0xffffffffu, tm, 8));
            tm = fmaxf(tm, __shfl_xor_sync(0xffffffffu, tm, 16));
            const float mnew = fmaxf(m[r], tm);
            scl[r] = __expf(m[r] - mnew);
            float tl = 0.f;
#pragma unroll
            for (int i = 0; i < 4; i++) { p8[r][i] = __expf(sv[i] - mnew); tl += p8[r][i]; }
            tl += __shfl_xor_sync(0xffffffffu, tl, 1);
            tl += __shfl_xor_sync(0xffffffffu, tl, 2);
            tl += __shfl_xor_sync(0xffffffffu, tl, 4);
            tl += __shfl_xor_sync(0xffffffffu, tl, 8);
            tl += __shfl_xor_sync(0xffffffffu, tl, 16);
            l[r] = l[r] * scl[r] + tl;
            m[r] = mnew;
        }
#pragma unroll
        for (int p = 0; p < 4; p++) {
            u64 sp = pack2(scl[2 * p], scl[2 * p + 1]);
            mul2(o2[p][0], sp);
            mul2(o2[p][1], sp);
        }
#pragma unroll
        for (int i = 0; i < 4; i++) {
            const int key = lane * 4 + i;
            *reinterpret_cast<float4*>(&sPt[key * PP2 + ty8]) =
                make_float4(p8[0][i], p8[1][i], p8[2][i], p8[3][i]);
            *reinterpret_cast<float4*>(&sPt[key * PP2 + ty8 + 4]) =
                make_float4(p8[4][i], p8[5][i], p8[6][i], p8[7][i]);
        }
        __syncthreads();

        const float* sV = smem + (cb == 0 ? B_V0 : B_V1) / 4;
#pragma unroll 8
        for (int j = 0; j < 128; j++) {
            ulonglong2 pA = *reinterpret_cast<const ulonglong2*>(&sPt[j * PP2 + ty8]);
            ulonglong2 pB = *reinterpret_cast<const ulonglong2*>(&sPt[j * PP2 + ty8 + 4]);
            float2 v2 = *reinterpret_cast<const float2*>(&sV[j * PV2 + lane * 2]);
            u64 v0 = splat2(v2.x), v1 = splat2(v2.y);
            fma2(o2[0][0], pA.x, v0); fma2(o2[0][1], pA.x, v1);
            fma2(o2[1][0], pA.y, v0); fma2(o2[1][1], pA.y, v1);
            fma2(o2[2][0], pB.x, v0); fma2(o2[2][1], pB.x, v1);
            fma2(o2[3][0], pB.y, v0); fma2(o2[3][1], pB.y, v1);
        }
    }

    if (lane == 0) {
#pragma unroll
        for (int r = 0; r < 8; r++) {
            g_pm[bid * 64 + ty8 + r] = m[r];
            g_pl[bid * 64 + ty8 + r] = l[r];
        }
    }
#pragma unroll
    for (int p = 0; p < 4; p++) {
        float aLo, aHi, bLo, bHi;
        unpack2(o2[p][0], aLo, aHi);
        unpack2(o2[p][1], bLo, bHi);
        *reinterpret_cast<float2*>(
            &g_po[(size_t)bid * 4096 + (ty8 + 2 * p) * 64 + lane * 2]) =
            make_float2(aLo, bLo);
        *reinterpret_cast<float2*>(
            &g_po[(size_t)bid * 4096 + (ty8 + 2 * p + 1) * 64 + lane * 2]) =
            make_float2(aHi, bHi);
    }
}

// ---------------------------------------------------------------------------
// Kernel F: merge partials (computes vmean inline from g_vpart).
// ---------------------------------------------------------------------------
__global__ __launch_bounds__(256) void attn_merge_kernel(float* __restrict__ out)
{
    const int b  = blockIdx.x >> 5;
    const int jq = blockIdx.x & 31;
    int off;
    if (jq < 8)       off = jq;
    else if (jq < 16) off = 8 + 2 * (jq - 8);
    else if (jq < 24) off = 24 + 3 * (jq - 16);
    else              off = 48 + 4 * (jq - 24);
    const int nch = (jq >> 3) + 1;
    const int jbase = b * 80 + off;
    const int q0 = jq * 64;

    const int d  = threadIdx.x & 63;
    const int r0 = threadIdx.x >> 6;

    // inline vmean (replaces vmean2 kernel)
    float vm = 0.f;
#pragma unroll 8
    for (int c = 0; c < 32; c++) vm += g_vpart[(b * 32 + c) * HD + d];
    vm *= (1.0f / SEQ);

    for (int rr = 0; rr < 16; rr++) {
        const int row = r0 + rr * 4;
        float M = -3.0e38f;
        float mi[5], li[5];
#pragma unroll 5
        for (int i = 0; i < 5; i++) {
            if (i < nch) {
                mi[i] = g_pm[(jbase + i) * 64 + row];
                li[i] = g_pl[(jbase + i) * 64 + row];
                M = fmaxf(M, mi[i]);
            }
        }
        float L = 0.f, O = 0.f;
#pragma unroll 5
        for (int i = 0; i < 5; i++) {
            if (i < nch) {
                float w = __expf(mi[i] - M);
                L += li[i] * w;
                O += g_po[(size_t)(jbase + i) * 4096 + row * 64 + d] * w;
            }
        }
        float res = (M <= -1.0e8f) ? vm : O / L;
        out[((size_t)b * SEQ + q0 + row) * HD + d] = res;
    }
}

// ---------------------------------------------------------------------------
extern "C" void kernel_launch(void* const* d_in, const int* in_sizes, int n_in,
                              void* d_out, int out_size)
{
    const float* x   = (const float*)d_in[0];
    const int*   pad = (const int*)  d_in[1];
    const float* Wq  = (const float*)d_in[2];
    const float* Wk  = (const float*)d_in[3];
    const float* Wv  = (const float*)d_in[4];
    float* out = (float*)d_out;

    cudaFuncSetAttribute(qkv_gemm_kernel,
                         cudaFuncAttributeMaxDynamicSharedMemorySize, GEMM_SMEM);
    cudaFuncSetAttribute(attn_partial_kernel,
                         cudaFuncAttributeMaxDynamicSharedMemorySize, ATTN_SMEM);

    convert_all_kernel<<<8384, 256>>>(x, Wq, Wk, Wv);
    qkv_gemm_kernel<<<128, 256, GEMM_SMEM>>>();
    vmean1_kernel<<<dim3(BSZ, 32), 256>>>();
    attn_partial_kernel<<<NJOBS, 256, ATTN_SMEM>>>(pad);
    attn_merge_kernel<<<128, 256>>>(out);
}